// round 13
// baseline (speedup 1.0000x reference)
#include <cuda_runtime.h>
#include <cuda_bf16.h>
#include <math.h>
#include <stdint.h>

#define B  32
#define LX 64
#define TT 64
#define D  1024
#define V  32000
#define KP 3072
#define GRIDN 128
// dynamic ring for k_steps: mbar@0 (32B) | A stages 3x8192 @32 | B stages 3x16384 @24608
#define SC_ABASE 32
#define SC_BBASE 24608
#define STEPS_DYN (32 + 3 * 8192 + 3 * 16384)
// dynamic smem for logits: A 2 stages x 10240 @0 | B 2 stages x 20480 @20480
#define LOGITS_DYN (2 * 10240 + 2 * 20480)

// ------------------- device globals --------------------------------------------
__device__ float g_c[B * D];
__device__ float g_gatesp2[4 * 64 * 4096];
__device__ float g_hprojp2[16 * 64 * 1024];
__device__ float g_prep2[16 * 64 * 1024];
__device__ float g_wl[B * LX];
// step-GEMM A operands, chunk-block layout [chunk][64][32] (4KB blocks)
__device__ __align__(16) __nv_bfloat16 g_A2g[256 * 64 * 32];
__device__ __align__(16) __nv_bfloat16 g_A2h[64 * 64 * 32];
__device__ __align__(16) __nv_bfloat16 g_A2p[192 * 64 * 32];
// logits operands (row-major)
__device__ __align__(16) __nv_bfloat16 g_Abf[(TT * B) * KP];
__device__ __align__(16) __nv_bfloat16 g_Bbf[(size_t)V * KP];
// weights, chunk-block layout [coltile][chunk][128][32] (8KB blocks)
__device__ __align__(16) __nv_bfloat16 g_Wg2[(size_t)32 * 256 * 128 * 32];
__device__ __align__(16) __nv_bfloat16 g_Wh2[8 * 64 * 128 * 32];
__device__ __align__(16) __nv_bfloat16 g_Wp2[8 * 192 * 128 * 32];
__device__ int g_flags[GRIDN];

// ------------------- helpers -----------------------------------------------------
__device__ __forceinline__ float fast_tanh(float x) {
    float e = __expf(2.f * x);
    return 1.f - __fdividef(2.f, e + 1.f);
}
__device__ __forceinline__ uint32_t smem_u32(const void* p) {
    uint32_t a;
    asm("{ .reg .u64 t; cvta.to.shared.u64 t, %1; cvt.u32.u64 %0, t; }" : "=r"(a) : "l"(p));
    return a;
}
__device__ __forceinline__ void cpasync16(uint32_t dst, const void* src) {
    asm volatile("cp.async.cg.shared.global [%0], [%1], 16;" :: "r"(dst), "l"(src));
}
__device__ __forceinline__ void ldm_x4(uint32_t* r, uint32_t addr) {
    asm volatile("ldmatrix.sync.aligned.m8n8.x4.shared.b16 {%0,%1,%2,%3}, [%4];"
        : "=r"(r[0]), "=r"(r[1]), "=r"(r[2]), "=r"(r[3]) : "r"(addr));
}
__device__ __forceinline__ void mma_bf16(float* c, const uint32_t* a, const uint32_t* b) {
    asm volatile("mma.sync.aligned.m16n8k16.row.col.f32.bf16.bf16.f32 "
        "{%0,%1,%2,%3}, {%4,%5,%6,%7}, {%8,%9}, {%0,%1,%2,%3};"
        : "+f"(c[0]), "+f"(c[1]), "+f"(c[2]), "+f"(c[3])
        : "r"(a[0]), "r"(a[1]), "r"(a[2]), "r"(a[3]), "r"(b[0]), "r"(b[1]));
}
__device__ __forceinline__ void split_bf(float v, __nv_bfloat16& hi, __nv_bfloat16& lo) {
    hi = __float2bfloat16_rn(v);
    lo = __float2bfloat16_rn(v - __bfloat162float(hi));
}
__device__ __forceinline__ int swoff(int row, int kin) {
    return ((((kin >> 3) ^ ((row >> 1) & 3)) << 3) | (kin & 7));
}
__device__ __forceinline__ void a2st(__nv_bfloat16* base, int row, int k, __nv_bfloat16 v) {
    base[((k >> 5) * 64 + row) * 32 + swoff(row, k & 31)] = v;
}
__device__ __forceinline__ void w2st(__nv_bfloat16* base, int nch, int j, int k,
                                     __nv_bfloat16 v) {
    base[(size_t)(((j >> 7) * nch + (k >> 5)) * 128 + (j & 127)) * 32
         + swoff(j & 127, k & 31)] = v;
}
// ------------------- bulk copy + mbarrier ------------------------------------------
__device__ __forceinline__ void bulk_g2s(uint32_t dst, const void* src, uint32_t bytes,
                                         uint32_t mbar) {
    asm volatile(
        "cp.async.bulk.shared::cluster.global.mbarrier::complete_tx::bytes [%0], [%1], %2, [%3];"
        :: "r"(dst), "l"(src), "r"(bytes), "r"(mbar) : "memory");
}
__device__ __forceinline__ void mbar_expect(uint32_t mbar, uint32_t bytes) {
    asm volatile("mbarrier.arrive.expect_tx.shared.b64 _, [%0], %1;"
                 :: "r"(mbar), "r"(bytes) : "memory");
}
__device__ __forceinline__ void mbar_init1(uint32_t mbar) {
    asm volatile("mbarrier.init.shared.b64 [%0], 1;" :: "r"(mbar) : "memory");
}
__device__ __forceinline__ void mbar_wait(uint32_t mbar, uint32_t parity) {
    asm volatile(
        "{\n\t.reg .pred P;\n"
        "W%=:\n\t"
        "mbarrier.try_wait.parity.shared.b64 P, [%0], %1;\n\t"
        "@P bra D%=;\n\t"
        "bra W%=;\n"
        "D%=:\n\t}"
        :: "r"(mbar), "r"(parity) : "memory");
}
// issue one SUPER-chunk (two contiguous 32-k blocks) into ring stage idx%3
__device__ __forceinline__ void issue_super(uint32_t sb, unsigned idx,
        const __nv_bfloat16* __restrict__ Ablk,
        const __nv_bfloat16* __restrict__ Bblk, int chunk) {
    uint32_t st = idx % 3u, mb = sb + st * 8u;
    mbar_expect(mb, 24576u);
    bulk_g2s(sb + SC_ABASE + st * 8192u, Ablk + (size_t)chunk * 2048, 8192u, mb);
    bulk_g2s(sb + SC_BBASE + st * 16384u, Bblk + (size_t)chunk * 4096, 16384u, mb);
}
// ------------------- flag-array grid barrier -----------------------------------------
__device__ __forceinline__ void gridbar(unsigned gen) {
    asm volatile("fence.proxy.async;" ::: "memory");
    __threadfence();
    __syncthreads();
    if (threadIdx.x == 0) atomicExch(&g_flags[blockIdx.x], (int)gen);
    bool ok;
    do {
        ok = (threadIdx.x >= GRIDN) ||
             (__ldcg(&g_flags[threadIdx.x]) >= (int)gen);
    } while (!__syncthreads_and(ok));
}

// ------------------- init -----------------------------------------------------------
__global__ void k_init0(const float* __restrict__ h0, const float* __restrict__ c0,
                        const float* __restrict__ word_emb,
                        const int* __restrict__ y_train) {
    int i = blockIdx.x * 256 + threadIdx.x;
    if (i < GRIDN) g_flags[i] = 0;
    if (i < 64 * 8192) {                 // gates A2 for t=0
        int r = i >> 13, k = i & 8191;
        int b = r & 31;
        bool isLo = r >= 32;
        int ks = (k < 4096) ? k : k - 4096;
        float v = 0.f;
        bool zero = (isLo && k >= 4096);
        if (!zero) {
            if (ks < 1024) {
                int y = y_train[b * TT + 0];
                v = word_emb[(size_t)y * D + ks];
            } else if (ks < 3072) {
                v = 0.f;
            } else {
                v = h0[b * D + (ks - 3072)];
            }
        }
        __nv_bfloat16 hi, lo; split_bf(v, hi, lo);
        a2st(g_A2g, r, k, zero ? __float2bfloat16_rn(0.f) : (isLo ? lo : hi));
        return;
    }
    int j = i - 64 * 8192;
    if (j < 32 * 1024) {
        int r = 32 + (j >> 10), k = 1024 + (j & 1023);
        a2st(g_A2h, r, k, __float2bfloat16_rn(0.f));
        return;
    }
    j -= 32 * 1024;
    if (j < 32 * 3072) {
        int r = 32 + j / 3072, k = 3072 + j % 3072;
        a2st(g_A2p, r, k, __float2bfloat16_rn(0.f));
        return;
    }
    j -= 32 * 3072;
    if (j < B * D) g_c[j] = c0[j];
}

// ------------------- weight conversions ----------------------------------------------
__global__ void k_convB(const float* __restrict__ RW) {
    int i = blockIdx.x * 256 + threadIdx.x;
    float v = RW[i];
    int r = i >> 10, d = i & 1023;
    __nv_bfloat16 hi, lo; split_bf(v, hi, lo);
    __nv_bfloat16* row = g_Bbf + (size_t)r * KP;
    row[d] = hi; row[1024 + d] = hi; row[2048 + d] = lo;
}
__global__ void k_convWg(const float* __restrict__ Wih, const float* __restrict__ Whh) {
    int k = blockIdx.x * 256 + threadIdx.x;
    int j = blockIdx.y;
    float v = (k < 3072) ? Wih[(size_t)j * 3072 + k] : Whh[(size_t)j * 1024 + (k - 3072)];
    __nv_bfloat16 hi, lo; split_bf(v, hi, lo);
    w2st(g_Wg2, 256, j, k, hi);
    w2st(g_Wg2, 256, j, 4096 + k, lo);
}
__global__ void k_convWh(const float* __restrict__ Wt) {
    int k = blockIdx.x * 256 + threadIdx.x;
    int j = blockIdx.y;
    float v = Wt[(size_t)j * 1024 + k];
    __nv_bfloat16 hi, lo; split_bf(v, hi, lo);
    w2st(g_Wh2, 64, j, k, hi);
    w2st(g_Wh2, 64, j, 1024 + k, lo);
}
__global__ void k_convWp(const float* __restrict__ Cw) {
    int k = blockIdx.x * 256 + threadIdx.x;
    int j = blockIdx.y;
    float v = Cw[(size_t)j * 3072 + k];
    __nv_bfloat16 hi, lo; split_bf(v, hi, lo);
    w2st(g_Wp2, 192, j, k, hi);
    w2st(g_Wp2, 192, j, 3072 + k, lo);
}

// ------------------- super-chunk 64xK @ Kx128 MMA phase -------------------------------
__device__ void mma_phase_bulk(uint32_t sb, unsigned& gsc,
        const __nv_bfloat16* __restrict__ Ablk,
        const __nv_bfloat16* __restrict__ Bblk,
        float* __restrict__ part, int ncols,
        int nsuper, int chunk0, int col0, int split, bool pre_issued) {
    int tid = threadIdx.x;
    int lane = tid & 31, wid = tid >> 5;
    int warpM = wid & 1, warpN = wid >> 1;

    int a_row = (lane & 7) + ((lane >> 3) & 1) * 8;
    int ca0 = lane >> 4;
    int b_row = (lane & 7) + (lane >> 4) * 8;
    int cb0 = (lane >> 3) & 1;
    int rA[2], sA_[2], rB[2], sB_[2];
#pragma unroll
    for (int mt = 0; mt < 2; mt++) {
        int r = warpM * 32 + mt * 16 + a_row;
        rA[mt] = r * 64; sA_[mt] = (r >> 1) & 3;
    }
#pragma unroll
    for (int p = 0; p < 2; p++) {
        int r = warpN * 32 + p * 16 + b_row;
        rB[p] = r * 64; sB_[p] = (r >> 1) & 3;
    }

    float acc[2][4][4] = {};

    if (!pre_issued && tid == 0) {
        issue_super(sb, gsc, Ablk, Bblk, chunk0);
        if (nsuper > 1) issue_super(sb, gsc + 1, Ablk, Bblk, chunk0 + 2);
    }
    for (int i = 0; i < nsuper; i++) {
        if (i + 2 < nsuper && tid == 0)
            issue_super(sb, gsc + (unsigned)(i + 2), Ablk, Bblk, chunk0 + 2 * (i + 2));
        unsigned idx = gsc + (unsigned)i;
        uint32_t st = idx % 3u;
        mbar_wait(sb + st * 8u, (idx / 3u) & 1u);
#pragma unroll
        for (int sub = 0; sub < 2; sub++) {
            uint32_t aOff = sb + SC_ABASE + st * 8192u + sub * 4096u;
            uint32_t bOff = sb + SC_BBASE + st * 16384u + sub * 8192u;
#pragma unroll
            for (int k16 = 0; k16 < 2; k16++) {
                int ca = ca0 + 2 * k16, cb = cb0 + 2 * k16;
                uint32_t a0[4], a1[4], bb[2][4];
                ldm_x4(a0, aOff + rA[0] + ((ca ^ sA_[0]) << 4));
                ldm_x4(a1, aOff + rA[1] + ((ca ^ sA_[1]) << 4));
                ldm_x4(bb[0], bOff + rB[0] + ((cb ^ sB_[0]) << 4));
                ldm_x4(bb[1], bOff + rB[1] + ((cb ^ sB_[1]) << 4));
#pragma unroll
                for (int nt = 0; nt < 4; nt++) {
                    mma_bf16(acc[0][nt], a0, &bb[nt >> 1][(nt & 1) * 2]);
                    mma_bf16(acc[1][nt], a1, &bb[nt >> 1][(nt & 1) * 2]);
                }
            }
        }
        __syncthreads();
    }
    gsc += (unsigned)nsuper;

    int grp = lane >> 2, tig = lane & 3;
#pragma unroll
    for (int mt = 0; mt < 2; mt++) {
        int m1 = warpM * 32 + mt * 16 + grp;
        int m2 = m1 + 8;
        float* p1 = part + (size_t)(split * 64 + m1) * ncols + col0 + warpN * 32;
        float* p2 = part + (size_t)(split * 64 + m2) * ncols + col0 + warpN * 32;
#pragma unroll
        for (int nt = 0; nt < 4; nt++) {
            int n = nt * 8 + tig * 2;
            *(float2*)(p1 + n) = make_float2(acc[mt][nt][0], acc[mt][nt][1]);
            *(float2*)(p2 + n) = make_float2(acc[mt][nt][2], acc[mt][nt][3]);
        }
    }
}

// ------------------- scalar phase work ------------------------------------------------
__device__ void emb_prefetch(int b, int tnext, const float* __restrict__ word_emb,
                             const int* __restrict__ y_train) {
    int d = threadIdx.x * 4;
    int y = y_train[b * TT + tnext];
    float4 v = *(const float4*)(word_emb + (size_t)y * D + d);
    float vv[4] = {v.x, v.y, v.z, v.w};
#pragma unroll
    for (int q = 0; q < 4; q++) {
        __nv_bfloat16 hi, lo; split_bf(vv[q], hi, lo);
        int k = d + q;
        a2st(g_A2g, b, k, hi); a2st(g_A2g, b, 4096 + k, hi); a2st(g_A2g, 32 + b, k, lo);
    }
}

__device__ void cell_work(int bid, const float* __restrict__ b_ih,
                          const float* __restrict__ b_hh) {
    int tid = threadIdx.x;
    if (tid >= 64) return;
    int m = bid >> 2;
    int d = (bid & 3) * 256 + tid * 4;
    int id = m * 1024 + d;
    float gv[4][4];
#pragma unroll
    for (int g = 0; g < 4; g++) {
        float4 bi = *(const float4*)(b_ih + g * 1024 + d);
        float4 bh = *(const float4*)(b_hh + g * 1024 + d);
        gv[g][0] = bi.x + bh.x; gv[g][1] = bi.y + bh.y;
        gv[g][2] = bi.z + bh.z; gv[g][3] = bi.w + bh.w;
    }
#pragma unroll
    for (int s = 0; s < 4; s++) {
#pragma unroll
        for (int g = 0; g < 4; g++) {
            float4 p0 = __ldcg((const float4*)(g_gatesp2
                         + (size_t)(s * 64 + m) * 4096 + g * 1024 + d));
            float4 p1 = __ldcg((const float4*)(g_gatesp2
                         + (size_t)(s * 64 + 32 + m) * 4096 + g * 1024 + d));
            gv[g][0] += p0.x; gv[g][0] += p1.x;
            gv[g][1] += p0.y; gv[g][1] += p1.y;
            gv[g][2] += p0.z; gv[g][2] += p1.z;
            gv[g][3] += p0.w; gv[g][3] += p1.w;
        }
    }
    float4 cold = __ldcg((const float4*)&g_c[id]);
    float co[4] = {cold.x, cold.y, cold.z, cold.w};
    float4 cnew;
    float* cn = (float*)&cnew;
#pragma unroll
    for (int q = 0; q < 4; q++) {
        float si = 1.f / (1.f + expf(-gv[0][q]));
        float sf = 1.f / (1.f + expf(-gv[1][q]));
        float so = 1.f / (1.f + expf(-gv[3][q]));
        float c = sf * co[q] + si * tanhf(gv[2][q]);
        cn[q] = c;
        float h = so * tanhf(c);
        __nv_bfloat16 hh, hl; split_bf(h, hh, hl);
        int dd = d + q;
        a2st(g_A2h, m, dd, hh);        a2st(g_A2h, m, 1024 + dd, hh);
        a2st(g_A2h, 32 + m, dd, hl);
        a2st(g_A2p, m, dd, hh);        a2st(g_A2p, m, 3072 + dd, hh);
        a2st(g_A2p, 32 + m, dd, hl);
        a2st(g_A2g, m, 3072 + dd, hh); a2st(g_A2g, m, 7168 + dd, hh);
        a2st(g_A2g, 32 + m, 3072 + dd, hl);
    }
    *(float4*)&g_c[id] = cnew;
}

__device__ void pretanh_work(int t, int bid) {
    int tid = threadIdx.x;
    if (tid >= 64) return;
    int m = bid >> 2;
    int d = (bid & 3) * 256 + tid * 4;
    float v[4] = {0.f, 0.f, 0.f, 0.f};
#pragma unroll
    for (int s = 0; s < 16; s++) {
        float4 p0 = __ldcg((const float4*)(g_prep2 + (size_t)(s * 64 + m) * 1024 + d));
        float4 p1 = __ldcg((const float4*)(g_prep2 + (size_t)(s * 64 + 32 + m) * 1024 + d));
        v[0] += p0.x; v[0] += p1.x;
        v[1] += p0.y; v[1] += p1.y;
        v[2] += p0.z; v[2] += p1.z;
        v[3] += p0.w; v[3] += p1.w;
    }
    int row = t * B + m;
    __nv_bfloat16* arow = g_Abf + (size_t)row * KP;
#pragma unroll
    for (int q = 0; q < 4; q++) {
        float tv = tanhf(v[q]);
        __nv_bfloat16 hi, lo; split_bf(tv, hi, lo);
        int dd = d + q;
        arow[dd] = hi; arow[1024 + dd] = lo; arow[2048 + dd] = hi;
    }
}

__device__ void attn_scores(int bid, float* s_hp,
                            const float* __restrict__ x_enc_k,
                            const unsigned char* __restrict__ xm,
                            const float* __restrict__ w_trg_b,
                            const float* __restrict__ w_att,
                            const float* __restrict__ w_att_b) {
    int b = bid >> 2;
    int q = bid & 3;
    int tid = threadIdx.x;
    int lane = tid & 31, wd = tid >> 5;
    {
        int d4 = tid * 4;
        float4 bi = *(const float4*)(w_trg_b + d4);
        float sum[4] = {bi.x, bi.y, bi.z, bi.w};
#pragma unroll
        for (int s = 0; s < 16; s++) {
            float4 p0 = __ldcg((const float4*)(g_hprojp2
                        + (size_t)(s * 64 + b) * 1024 + d4));
            float4 p1 = __ldcg((const float4*)(g_hprojp2
                        + (size_t)(s * 64 + 32 + b) * 1024 + d4));
            sum[0] += p0.x; sum[0] += p1.x;
            sum[1] += p0.y; sum[1] += p1.y;
            sum[2] += p0.z; sum[2] += p1.z;
            sum[3] += p0.w; sum[3] += p1.w;
        }
        *(float4*)&s_hp[d4] = make_float4(sum[0], sum[1], sum[2], sum[3]);
    }
    __syncthreads();
    for (int l = q * 16 + wd; l < q * 16 + 16; l += 8) {
        const float* xk = x_enc_k + ((size_t)(b * LX + l)) * D;
        float s = 0.f;
#pragma unroll 8
        for (int i = 0; i < 32; i++) {
            int d = lane + i * 32;
            s += fast_tanh(xk[d] + s_hp[d]) * w_att[d];
        }
#pragma unroll
        for (int off = 16; off; off >>= 1) s += __shfl_xor_sync(0xffffffffu, s, off);
        if (lane == 0) {
            float tot = s + w_att_b[0];
            if (xm[b * LX + l]) tot = -1e9f;
            g_wl[b * LX + l] = tot;
        }
    }
}

__device__ void attn_ctx(int bid, float* s_hp, float* s_wl,
                         const float* __restrict__ x_enc) {
    int b = bid >> 2;
    int quarter = bid & 3;
    int tid = threadIdx.x;
    if (tid == 0) {
        float tmp[LX];
        float mx = -1e30f;
        for (int l = 0; l < LX; l++) {
            float v = __ldcg(&g_wl[b * LX + l]);
            tmp[l] = v;
            mx = fmaxf(mx, v);
        }
        float z = 0.f;
        for (int l = 0; l < LX; l++) { float e = expf(tmp[l] - mx); tmp[l] = e; z += e; }
        float inv = 1.f / z;
        for (int l = 0; l < LX; l++) s_wl[l] = tmp[l] * inv;
    }
    __syncthreads();
    {
        int half = tid >> 7;
        int dt = (tid & 127) * 4;
        int d2 = quarter * 512 + dt;
        const float* xe = x_enc + (size_t)b * LX * 2048 + d2;
        float f[4] = {0.f, 0.f, 0.f, 0.f};
        int l0 = half * 32;
#pragma unroll 8
        for (int l = l0; l < l0 + 32; l++) {
            float w = s_wl[l];
            float4 x0 = *(const float4*)(xe + (size_t)l * 2048);
            f[0] += w * x0.x; f[1] += w * x0.y; f[2] += w * x0.z; f[3] += w * x0.w;
        }
        if (half == 0) {
            *(float4*)&s_hp[dt] = make_float4(f[0], f[1], f[2], f[3]);
        }
        __syncthreads();
        if (half == 1) {
            float4 o = *(const float4*)&s_hp[dt];
            f[0] += o.x; f[1] += o.y; f[2] += o.z; f[3] += o.w;
#pragma unroll
            for (int q = 0; q < 4; q++) {
                int dd = 1024 + d2 + q;
                __nv_bfloat16 hi, lo; split_bf(f[q], hi, lo);
                a2st(g_A2p, b, dd, hi);   a2st(g_A2p, b, 3072 + dd, hi);
                a2st(g_A2p, 32 + b, dd, lo);
                a2st(g_A2g, b, dd, hi);   a2st(g_A2g, b, 4096 + dd, hi);
                a2st(g_A2g, 32 + b, dd, lo);
            }
        }
    }
}

// ------------------- persistent step kernel (byte-identical to R12) -------------------
__global__ void __launch_bounds__(256, 1) k_steps(
    const float* __restrict__ x_enc, const float* __restrict__ x_enc_k,
    const unsigned char* __restrict__ xm, const int* __restrict__ y_train,
    const float* __restrict__ word_emb,
    const float* __restrict__ b_ih, const float* __restrict__ b_hh,
    const float* __restrict__ w_trg_b, const float* __restrict__ w_att,
    const float* __restrict__ w_att_b) {
    extern __shared__ __align__(128) char s_ring[];
    __shared__ float s_hp[1024];
    __shared__ float s_wl[LX];
    uint32_t sb = smem_u32(s_ring);
    int bid = blockIdx.x;
    int tid = threadIdx.x;
    unsigned gen = 0, gsc = 0;

    if (tid == 0) { mbar_init1(sb); mbar_init1(sb + 8); mbar_init1(sb + 16); }
    __syncthreads();

    const __nv_bfloat16* Wg = g_Wg2 + (size_t)(bid & 31) * 256 * 4096;
    int g_chunk0 = (bid >> 5) * 64;

    for (int t = 0; t < TT; t++) {
        // phase 1: gates MMA (32 super-chunks)
        if (tid == 0) {
            issue_super(sb, gsc, g_A2g, Wg, g_chunk0);
            issue_super(sb, gsc + 1, g_A2g, Wg, g_chunk0 + 2);
        }
        mma_phase_bulk(sb, gsc, g_A2g, Wg, g_gatesp2, 4096, 32,
                       g_chunk0, (bid & 31) * 128, bid >> 5, true);
        gridbar(++gen);
        // phase 2: LSTM cell + pretanh(t-1) + emb(t+1)
        cell_work(bid, b_ih, b_hh);
        if (t > 0) pretanh_work(t - 1, bid);
        if (bid < 32 && t + 1 < TT) emb_prefetch(bid, t + 1, word_emb, y_train);
        gridbar(++gen);
        // phase 3: hproj MMA (2 super-chunks)
        mma_phase_bulk(sb, gsc, g_A2h,
                       g_Wh2 + (size_t)(bid & 7) * 64 * 4096,
                       g_hprojp2, 1024, 2, (bid >> 3) * 4, (bid & 7) * 128,
                       bid >> 3, false);
        gridbar(++gen);
        // phase 4a: scores
        attn_scores(bid, s_hp, x_enc_k, xm, w_trg_b, w_att, w_att_b);
        gridbar(++gen);
        // phase 4b: softmax + ctx
        attn_ctx(bid, s_hp, s_wl, x_enc);
        gridbar(++gen);
        // phase 5: pre MMA (6 super-chunks, no trailing barrier)
        mma_phase_bulk(sb, gsc, g_A2p,
                       g_Wp2 + (size_t)(bid & 7) * 192 * 4096,
                       g_prep2, 1024, 6, (bid >> 3) * 12, (bid & 7) * 128,
                       bid >> 3, false);
    }
    gridbar(++gen);
    pretanh_work(TT - 1, bid);
}

// ------------------- logits GEMM: 128x256 tile, 512 threads, dynamic smem --------------
__global__ void __launch_bounds__(512, 1) k_logits_mma(float* __restrict__ out) {
    extern __shared__ __align__(128) char s_dyn[];
    uint32_t base = smem_u32(s_dyn);
    // A: 2 stages x 128 rows x 80B @0; B: 2 stages x 256 rows x 80B @20480
    int tid = threadIdx.x;
    int lane = tid & 31, wid = tid >> 5;
    int warpM = wid & 1, warpN = wid >> 1;   // 2(M) x 8(N)
    int row0 = blockIdx.x * 128;
    int col0 = blockIdx.y * 256;

    int a_row = (lane & 7) + ((lane >> 3) & 1) * 8;
    int a_k   = (lane >> 4) * 8;
    int b_row = (lane & 7) + (lane >> 4) * 8;
    int b_k   = ((lane >> 3) & 1) * 8;
    uint32_t aBase = base + (warpM * 64 + a_row) * 80 + a_k * 2;
    uint32_t bBase = base + 20480 + (warpN * 32 + b_row) * 80 + b_k * 2;

    int ar = tid >> 2, ali = tid & 3;        // A: 512 16B-chunks, 1/thread

    float acc[4][4][4];
#pragma unroll
    for (int i = 0; i < 4; i++)
#pragma unroll
        for (int j = 0; j < 4; j++)
#pragma unroll
            for (int q = 0; q < 4; q++) acc[i][j][q] = 0.f;

    // prologue: stage 0 of k-chunk 0
    cpasync16(base + ar * 80 + ali * 16, g_Abf + (size_t)(row0 + ar) * KP + ali * 8);
#pragma unroll
    for (int q = 0; q < 2; q++) {
        int idx = q * 512 + tid;
        int br = idx >> 2, bli = idx & 3;
        cpasync16(base + 20480 + br * 80 + bli * 16,
                  g_Bbf + (size_t)(col0 + br) * KP + bli * 8);
    }
    asm volatile("cp.async.commit_group;" ::: "memory");

    const int NCH = KP / 32;
    for (int i = 0; i < NCH; i++) {
        int st = i & 1;
        if (i + 1 < NCH) {
            int ns = st ^ 1;
            int kb = (i + 1) * 32;
            cpasync16(base + ns * 10240 + ar * 80 + ali * 16,
                      g_Abf + (size_t)(row0 + ar) * KP + kb + ali * 8);
#pragma unroll
            for (int q = 0; q < 2; q++) {
                int idx = q * 512 + tid;
                int br = idx >> 2, bli = idx & 3;
                cpasync16(base + 20480 + ns * 20480 + br * 80 + bli * 16,
                          g_Bbf + (size_t)(col0 + br) * KP + kb + bli * 8);
            }
            asm volatile("cp.async.commit_group;" ::: "memory");
            asm volatile("cp.async.wait_group 1;" ::: "memory");
        } else {
            asm volatile("cp.async.wait_group 0;" ::: "memory");
        }
        __syncthreads();

        uint32_t aSt = st * 10240u, bSt = st * 20480u;
#pragma unroll
        for (int k16 = 0; k16 < 2; k16++) {
            uint32_t koff = k16 * 32;
            uint32_t a[4][4], b[2][4];
#pragma unroll
            for (int mt = 0; mt < 4; mt++)
                ldm_x4(a[mt], aBase + aSt + koff + mt * 1280);
#pragma unroll
            for (int p = 0; p < 2; p++)
                ldm_x4(b[p], bBase + bSt + koff + p * 1280);
#pragma unroll
            for (int mt = 0; mt < 4; mt++)
#pragma unroll
                for (int nt = 0; nt < 4; nt++)
                    mma_bf16(acc[mt][nt], a[mt], &b[nt >> 1][(nt & 1) * 2]);
        }
        __syncthreads();
    }

    int grp = lane >> 2, tig = lane & 3;
#pragma unroll
    for (int mt = 0; mt < 4; mt++) {
        int m1 = row0 + warpM * 64 + mt * 16 + grp;
        int m2 = m1 + 8;
        float* o1 = out + ((size_t)(m1 & 31) * TT + (m1 >> 5)) * V;
        float* o2 = out + ((size_t)(m2 & 31) * TT + (m2 >> 5)) * V;
#pragma unroll
        for (int nt = 0; nt < 4; nt++) {
            int n = col0 + warpN * 32 + nt * 8 + tig * 2;
            *(float2*)(o1 + n) = make_float2(acc[mt][nt][0], acc[mt][nt][1]);
            *(float2*)(o2 + n) = make_float2(acc[mt][nt][2], acc[mt][nt][3]);
        }
    }
}

// ------------------- launch ---------------------------------------------------------------
extern "C" void kernel_launch(void* const* d_in, const int* in_sizes, int n_in,
                              void* d_out, int out_size) {
    const float* x_enc      = (const float*)d_in[0];
    const float* x_enc_k    = (const float*)d_in[1];
    const float* h0         = (const float*)d_in[2];
    const float* c0         = (const float*)d_in[3];
    const unsigned char* xm = (const unsigned char*)d_in[4];
    const int*   y_train    = (const int*)d_in[5];
    const float* word_emb   = (const float*)d_in[6];
    const float* W_ih       = (const float*)d_in[7];
    const float* W_hh       = (const float*)d_in[8];
    const float* b_ih       = (const float*)d_in[9];
    const float* b_hh       = (const float*)d_in[10];
    const float* w_trg_W    = (const float*)d_in[11];
    const float* w_trg_b    = (const float*)d_in[12];
    const float* w_att      = (const float*)d_in[13];
    const float* w_att_b    = (const float*)d_in[14];
    const float* ctx_W      = (const float*)d_in[15];
    const float* RW         = (const float*)d_in[16];
    float* out = (float*)d_out;

    cudaFuncSetAttribute(k_steps, cudaFuncAttributeMaxDynamicSharedMemorySize, STEPS_DYN);
    cudaFuncSetAttribute(k_logits_mma, cudaFuncAttributeMaxDynamicSharedMemorySize,
                         LOGITS_DYN);

    k_convB<<<(V * D) / 256, 256>>>(RW);
    k_convWg<<<dim3(16, 4096), 256>>>(W_ih, W_hh);
    k_convWh<<<dim3(4, 1024), 256>>>(w_trg_W);
    k_convWp<<<dim3(12, 1024), 256>>>(ctx_W);
    int init_total = 64 * 8192 + 32 * 1024 + 32 * 3072 + B * D;
    k_init0<<<(init_total + 255) / 256, 256>>>(h0, c0, word_emb, y_train);
    k_steps<<<GRIDN, 256, STEPS_DYN>>>(x_enc, x_enc_k, xm, y_train, word_emb,
                                       b_ih, b_hh, w_trg_b, w_att, w_att_b);
    k_logits_mma<<<dim3((B * TT) / 128, V / 256), 512, LOGITS_DYN>>>(out);
}

// round 14
// speedup vs baseline: 1.0457x; 1.0457x over previous
#include <cuda_runtime.h>
#include <cuda_bf16.h>
#include <math.h>
#include <stdint.h>

#define B  32
#define LX 64
#define TT 64
#define D  1024
#define V  32000
#define KPA 2048        // dedup A': [hi|lo]
#define KPB 2048        // dedup B': [hi|lo]
#define GRIDN 128
// dynamic ring for k_steps: mbar@0 (32B) | A stages 3x8192 @32 | B stages 3x16384 @24608
#define SC_ABASE 32
#define SC_BBASE 24608
#define STEPS_DYN (32 + 3 * 8192 + 3 * 16384)

// ------------------- device globals --------------------------------------------
__device__ float g_c[B * D];
__device__ float g_gatesp2[4 * 64 * 4096];
__device__ float g_hprojp2[16 * 64 * 1024];
__device__ float g_prep2[16 * 64 * 1024];
__device__ float g_wl[B * LX];
// step-GEMM A operands, chunk-block layout [chunk][64][32] (4KB blocks)
__device__ __align__(16) __nv_bfloat16 g_A2g[256 * 64 * 32];
__device__ __align__(16) __nv_bfloat16 g_A2h[64 * 64 * 32];
__device__ __align__(16) __nv_bfloat16 g_A2p[192 * 64 * 32];
// logits operands (row-major, dedup [hi|lo])
__device__ __align__(16) __nv_bfloat16 g_Abf[(TT * B) * KPA];
__device__ __align__(16) __nv_bfloat16 g_Bbf[(size_t)V * KPB];
// weights, chunk-block layout [coltile][chunk][128][32] (8KB blocks)
__device__ __align__(16) __nv_bfloat16 g_Wg2[(size_t)32 * 256 * 128 * 32];
__device__ __align__(16) __nv_bfloat16 g_Wh2[8 * 64 * 128 * 32];
__device__ __align__(16) __nv_bfloat16 g_Wp2[8 * 192 * 128 * 32];
__device__ int g_flags[GRIDN];

// ------------------- helpers -----------------------------------------------------
__device__ __forceinline__ float fast_tanh(float x) {
    float e = __expf(2.f * x);
    return 1.f - __fdividef(2.f, e + 1.f);
}
__device__ __forceinline__ uint32_t smem_u32(const void* p) {
    uint32_t a;
    asm("{ .reg .u64 t; cvta.to.shared.u64 t, %1; cvt.u32.u64 %0, t; }" : "=r"(a) : "l"(p));
    return a;
}
__device__ __forceinline__ void cpasync16(uint32_t dst, const void* src) {
    asm volatile("cp.async.cg.shared.global [%0], [%1], 16;" :: "r"(dst), "l"(src));
}
__device__ __forceinline__ void ldm_x4(uint32_t* r, uint32_t addr) {
    asm volatile("ldmatrix.sync.aligned.m8n8.x4.shared.b16 {%0,%1,%2,%3}, [%4];"
        : "=r"(r[0]), "=r"(r[1]), "=r"(r[2]), "=r"(r[3]) : "r"(addr));
}
__device__ __forceinline__ void mma_bf16(float* c, const uint32_t* a, const uint32_t* b) {
    asm volatile("mma.sync.aligned.m16n8k16.row.col.f32.bf16.bf16.f32 "
        "{%0,%1,%2,%3}, {%4,%5,%6,%7}, {%8,%9}, {%0,%1,%2,%3};"
        : "+f"(c[0]), "+f"(c[1]), "+f"(c[2]), "+f"(c[3])
        : "r"(a[0]), "r"(a[1]), "r"(a[2]), "r"(a[3]), "r"(b[0]), "r"(b[1]));
}
__device__ __forceinline__ void split_bf(float v, __nv_bfloat16& hi, __nv_bfloat16& lo) {
    hi = __float2bfloat16_rn(v);
    lo = __float2bfloat16_rn(v - __bfloat162float(hi));
}
__device__ __forceinline__ int swoff(int row, int kin) {
    return ((((kin >> 3) ^ ((row >> 1) & 3)) << 3) | (kin & 7));
}
__device__ __forceinline__ void a2st(__nv_bfloat16* base, int row, int k, __nv_bfloat16 v) {
    base[((k >> 5) * 64 + row) * 32 + swoff(row, k & 31)] = v;
}
__device__ __forceinline__ void w2st(__nv_bfloat16* base, int nch, int j, int k,
                                     __nv_bfloat16 v) {
    base[(size_t)(((j >> 7) * nch + (k >> 5)) * 128 + (j & 127)) * 32
         + swoff(j & 127, k & 31)] = v;
}
// ------------------- bulk copy + mbarrier ------------------------------------------
__device__ __forceinline__ void bulk_g2s(uint32_t dst, const void* src, uint32_t bytes,
                                         uint32_t mbar) {
    asm volatile(
        "cp.async.bulk.shared::cluster.global.mbarrier::complete_tx::bytes [%0], [%1], %2, [%3];"
        :: "r"(dst), "l"(src), "r"(bytes), "r"(mbar) : "memory");
}
__device__ __forceinline__ void mbar_expect(uint32_t mbar, uint32_t bytes) {
    asm volatile("mbarrier.arrive.expect_tx.shared.b64 _, [%0], %1;"
                 :: "r"(mbar), "r"(bytes) : "memory");
}
__device__ __forceinline__ void mbar_init1(uint32_t mbar) {
    asm volatile("mbarrier.init.shared.b64 [%0], 1;" :: "r"(mbar) : "memory");
}
__device__ __forceinline__ void mbar_wait(uint32_t mbar, uint32_t parity) {
    asm volatile(
        "{\n\t.reg .pred P;\n"
        "W%=:\n\t"
        "mbarrier.try_wait.parity.shared.b64 P, [%0], %1;\n\t"
        "@P bra D%=;\n\t"
        "bra W%=;\n"
        "D%=:\n\t}"
        :: "r"(mbar), "r"(parity) : "memory");
}
// issue one SUPER-chunk (two contiguous 32-k blocks) into ring stage idx%3
__device__ __forceinline__ void issue_super(uint32_t sb, unsigned idx,
        const __nv_bfloat16* __restrict__ Ablk,
        const __nv_bfloat16* __restrict__ Bblk, int chunk) {
    uint32_t st = idx % 3u, mb = sb + st * 8u;
    mbar_expect(mb, 24576u);
    bulk_g2s(sb + SC_ABASE + st * 8192u, Ablk + (size_t)chunk * 2048, 8192u, mb);
    bulk_g2s(sb + SC_BBASE + st * 16384u, Bblk + (size_t)chunk * 4096, 16384u, mb);
}
// ------------------- flag-array grid barrier -----------------------------------------
__device__ __forceinline__ void gridbar(unsigned gen) {
    asm volatile("fence.proxy.async;" ::: "memory");
    __threadfence();
    __syncthreads();
    if (threadIdx.x == 0) atomicExch(&g_flags[blockIdx.x], (int)gen);
    bool ok;
    do {
        ok = (threadIdx.x >= GRIDN) ||
             (__ldcg(&g_flags[threadIdx.x]) >= (int)gen);
    } while (!__syncthreads_and(ok));
}

// ------------------- init -----------------------------------------------------------
__global__ void k_init0(const float* __restrict__ h0, const float* __restrict__ c0,
                        const float* __restrict__ word_emb,
                        const int* __restrict__ y_train) {
    int i = blockIdx.x * 256 + threadIdx.x;
    if (i < GRIDN) g_flags[i] = 0;
    if (i < 64 * 8192) {                 // gates A2 for t=0
        int r = i >> 13, k = i & 8191;
        int b = r & 31;
        bool isLo = r >= 32;
        int ks = (k < 4096) ? k : k - 4096;
        float v = 0.f;
        bool zero = (isLo && k >= 4096);
        if (!zero) {
            if (ks < 1024) {
                int y = y_train[b * TT + 0];
                v = word_emb[(size_t)y * D + ks];
            } else if (ks < 3072) {
                v = 0.f;
            } else {
                v = h0[b * D + (ks - 3072)];
            }
        }
        __nv_bfloat16 hi, lo; split_bf(v, hi, lo);
        a2st(g_A2g, r, k, zero ? __float2bfloat16_rn(0.f) : (isLo ? lo : hi));
        return;
    }
    int j = i - 64 * 8192;
    if (j < 32 * 1024) {
        int r = 32 + (j >> 10), k = 1024 + (j & 1023);
        a2st(g_A2h, r, k, __float2bfloat16_rn(0.f));
        return;
    }
    j -= 32 * 1024;
    if (j < 32 * 3072) {
        int r = 32 + j / 3072, k = 3072 + j % 3072;
        a2st(g_A2p, r, k, __float2bfloat16_rn(0.f));
        return;
    }
    j -= 32 * 3072;
    if (j < B * D) g_c[j] = c0[j];
}

// ------------------- weight conversions ----------------------------------------------
__global__ void k_convB(const float* __restrict__ RW) {
    int i = blockIdx.x * 256 + threadIdx.x;
    float v = RW[i];
    int r = i >> 10, d = i & 1023;
    __nv_bfloat16 hi, lo; split_bf(v, hi, lo);
    __nv_bfloat16* row = g_Bbf + (size_t)r * KPB;
    row[d] = hi; row[1024 + d] = lo;
}
__global__ void k_convWg(const float* __restrict__ Wih, const float* __restrict__ Whh) {
    int k = blockIdx.x * 256 + threadIdx.x;
    int j = blockIdx.y;
    float v = (k < 3072) ? Wih[(size_t)j * 3072 + k] : Whh[(size_t)j * 1024 + (k - 3072)];
    __nv_bfloat16 hi, lo; split_bf(v, hi, lo);
    w2st(g_Wg2, 256, j, k, hi);
    w2st(g_Wg2, 256, j, 4096 + k, lo);
}
__global__ void k_convWh(const float* __restrict__ Wt) {
    int k = blockIdx.x * 256 + threadIdx.x;
    int j = blockIdx.y;
    float v = Wt[(size_t)j * 1024 + k];
    __nv_bfloat16 hi, lo; split_bf(v, hi, lo);
    w2st(g_Wh2, 64, j, k, hi);
    w2st(g_Wh2, 64, j, 1024 + k, lo);
}
__global__ void k_convWp(const float* __restrict__ Cw) {
    int k = blockIdx.x * 256 + threadIdx.x;
    int j = blockIdx.y;
    float v = Cw[(size_t)j * 3072 + k];
    __nv_bfloat16 hi, lo; split_bf(v, hi, lo);
    w2st(g_Wp2, 192, j, k, hi);
    w2st(g_Wp2, 192, j, 3072 + k, lo);
}

// ------------------- super-chunk 64xK @ Kx128 MMA phase -------------------------------
__device__ void mma_phase_bulk(uint32_t sb, unsigned& gsc,
        const __nv_bfloat16* __restrict__ Ablk,
        const __nv_bfloat16* __restrict__ Bblk,
        float* __restrict__ part, int ncols,
        int nsuper, int chunk0, int col0, int split, bool pre_issued) {
    int tid = threadIdx.x;
    int lane = tid & 31, wid = tid >> 5;
    int warpM = wid & 1, warpN = wid >> 1;

    int a_row = (lane & 7) + ((lane >> 3) & 1) * 8;
    int ca0 = lane >> 4;
    int b_row = (lane & 7) + (lane >> 4) * 8;
    int cb0 = (lane >> 3) & 1;
    int rA[2], sA_[2], rB[2], sB_[2];
#pragma unroll
    for (int mt = 0; mt < 2; mt++) {
        int r = warpM * 32 + mt * 16 + a_row;
        rA[mt] = r * 64; sA_[mt] = (r >> 1) & 3;
    }
#pragma unroll
    for (int p = 0; p < 2; p++) {
        int r = warpN * 32 + p * 16 + b_row;
        rB[p] = r * 64; sB_[p] = (r >> 1) & 3;
    }

    float acc[2][4][4] = {};

    if (!pre_issued && tid == 0) {
        issue_super(sb, gsc, Ablk, Bblk, chunk0);
        if (nsuper > 1) issue_super(sb, gsc + 1, Ablk, Bblk, chunk0 + 2);
    }
    for (int i = 0; i < nsuper; i++) {
        if (i + 2 < nsuper && tid == 0)
            issue_super(sb, gsc + (unsigned)(i + 2), Ablk, Bblk, chunk0 + 2 * (i + 2));
        unsigned idx = gsc + (unsigned)i;
        uint32_t st = idx % 3u;
        mbar_wait(sb + st * 8u, (idx / 3u) & 1u);
#pragma unroll
        for (int sub = 0; sub < 2; sub++) {
            uint32_t aOff = sb + SC_ABASE + st * 8192u + sub * 4096u;
            uint32_t bOff = sb + SC_BBASE + st * 16384u + sub * 8192u;
#pragma unroll
            for (int k16 = 0; k16 < 2; k16++) {
                int ca = ca0 + 2 * k16, cb = cb0 + 2 * k16;
                uint32_t a0[4], a1[4], bb[2][4];
                ldm_x4(a0, aOff + rA[0] + ((ca ^ sA_[0]) << 4));
                ldm_x4(a1, aOff + rA[1] + ((ca ^ sA_[1]) << 4));
                ldm_x4(bb[0], bOff + rB[0] + ((cb ^ sB_[0]) << 4));
                ldm_x4(bb[1], bOff + rB[1] + ((cb ^ sB_[1]) << 4));
#pragma unroll
                for (int nt = 0; nt < 4; nt++) {
                    mma_bf16(acc[0][nt], a0, &bb[nt >> 1][(nt & 1) * 2]);
                    mma_bf16(acc[1][nt], a1, &bb[nt >> 1][(nt & 1) * 2]);
                }
            }
        }
        __syncthreads();
    }
    gsc += (unsigned)nsuper;

    int grp = lane >> 2, tig = lane & 3;
#pragma unroll
    for (int mt = 0; mt < 2; mt++) {
        int m1 = warpM * 32 + mt * 16 + grp;
        int m2 = m1 + 8;
        float* p1 = part + (size_t)(split * 64 + m1) * ncols + col0 + warpN * 32;
        float* p2 = part + (size_t)(split * 64 + m2) * ncols + col0 + warpN * 32;
#pragma unroll
        for (int nt = 0; nt < 4; nt++) {
            int n = nt * 8 + tig * 2;
            *(float2*)(p1 + n) = make_float2(acc[mt][nt][0], acc[mt][nt][1]);
            *(float2*)(p2 + n) = make_float2(acc[mt][nt][2], acc[mt][nt][3]);
        }
    }
}

// ------------------- scalar phase work ------------------------------------------------
__device__ void emb_prefetch(int b, int tnext, const float* __restrict__ word_emb,
                             const int* __restrict__ y_train) {
    int d = threadIdx.x * 4;
    int y = y_train[b * TT + tnext];
    float4 v = *(const float4*)(word_emb + (size_t)y * D + d);
    float vv[4] = {v.x, v.y, v.z, v.w};
#pragma unroll
    for (int q = 0; q < 4; q++) {
        __nv_bfloat16 hi, lo; split_bf(vv[q], hi, lo);
        int k = d + q;
        a2st(g_A2g, b, k, hi); a2st(g_A2g, b, 4096 + k, hi); a2st(g_A2g, 32 + b, k, lo);
    }
}

__device__ void cell_work(int bid, const float* __restrict__ b_ih,
                          const float* __restrict__ b_hh) {
    int tid = threadIdx.x;
    if (tid >= 64) return;
    int m = bid >> 2;
    int d = (bid & 3) * 256 + tid * 4;
    int id = m * 1024 + d;
    float gv[4][4];
#pragma unroll
    for (int g = 0; g < 4; g++) {
        float4 bi = *(const float4*)(b_ih + g * 1024 + d);
        float4 bh = *(const float4*)(b_hh + g * 1024 + d);
        gv[g][0] = bi.x + bh.x; gv[g][1] = bi.y + bh.y;
        gv[g][2] = bi.z + bh.z; gv[g][3] = bi.w + bh.w;
    }
#pragma unroll
    for (int s = 0; s < 4; s++) {
#pragma unroll
        for (int g = 0; g < 4; g++) {
            float4 p0 = __ldcg((const float4*)(g_gatesp2
                         + (size_t)(s * 64 + m) * 4096 + g * 1024 + d));
            float4 p1 = __ldcg((const float4*)(g_gatesp2
                         + (size_t)(s * 64 + 32 + m) * 4096 + g * 1024 + d));
            gv[g][0] += p0.x; gv[g][0] += p1.x;
            gv[g][1] += p0.y; gv[g][1] += p1.y;
            gv[g][2] += p0.z; gv[g][2] += p1.z;
            gv[g][3] += p0.w; gv[g][3] += p1.w;
        }
    }
    float4 cold = __ldcg((const float4*)&g_c[id]);
    float co[4] = {cold.x, cold.y, cold.z, cold.w};
    float4 cnew;
    float* cn = (float*)&cnew;
#pragma unroll
    for (int q = 0; q < 4; q++) {
        float si = 1.f / (1.f + expf(-gv[0][q]));
        float sf = 1.f / (1.f + expf(-gv[1][q]));
        float so = 1.f / (1.f + expf(-gv[3][q]));
        float c = sf * co[q] + si * tanhf(gv[2][q]);
        cn[q] = c;
        float h = so * tanhf(c);
        __nv_bfloat16 hh, hl; split_bf(h, hh, hl);
        int dd = d + q;
        a2st(g_A2h, m, dd, hh);        a2st(g_A2h, m, 1024 + dd, hh);
        a2st(g_A2h, 32 + m, dd, hl);
        a2st(g_A2p, m, dd, hh);        a2st(g_A2p, m, 3072 + dd, hh);
        a2st(g_A2p, 32 + m, dd, hl);
        a2st(g_A2g, m, 3072 + dd, hh); a2st(g_A2g, m, 7168 + dd, hh);
        a2st(g_A2g, 32 + m, 3072 + dd, hl);
    }
    *(float4*)&g_c[id] = cnew;
}

__device__ void pretanh_work(int t, int bid) {
    int tid = threadIdx.x;
    if (tid >= 64) return;
    int m = bid >> 2;
    int d = (bid & 3) * 256 + tid * 4;
    float v[4] = {0.f, 0.f, 0.f, 0.f};
#pragma unroll
    for (int s = 0; s < 16; s++) {
        float4 p0 = __ldcg((const float4*)(g_prep2 + (size_t)(s * 64 + m) * 1024 + d));
        float4 p1 = __ldcg((const float4*)(g_prep2 + (size_t)(s * 64 + 32 + m) * 1024 + d));
        v[0] += p0.x; v[0] += p1.x;
        v[1] += p0.y; v[1] += p1.y;
        v[2] += p0.z; v[2] += p1.z;
        v[3] += p0.w; v[3] += p1.w;
    }
    int row = t * B + m;
    __nv_bfloat16* arow = g_Abf + (size_t)row * KPA;
#pragma unroll
    for (int q = 0; q < 4; q++) {
        float tv = tanhf(v[q]);
        __nv_bfloat16 hi, lo; split_bf(tv, hi, lo);
        int dd = d + q;
        arow[dd] = hi; arow[1024 + dd] = lo;
    }
}

__device__ void attn_scores(int bid, float* s_hp,
                            const float* __restrict__ x_enc_k,
                            const unsigned char* __restrict__ xm,
                            const float* __restrict__ w_trg_b,
                            const float* __restrict__ w_att,
                            const float* __restrict__ w_att_b) {
    int b = bid >> 2;
    int q = bid & 3;
    int tid = threadIdx.x;
    int lane = tid & 31, wd = tid >> 5;
    {
        int d4 = tid * 4;
        float4 bi = *(const float4*)(w_trg_b + d4);
        float sum[4] = {bi.x, bi.y, bi.z, bi.w};
#pragma unroll
        for (int s = 0; s < 16; s++) {
            float4 p0 = __ldcg((const float4*)(g_hprojp2
                        + (size_t)(s * 64 + b) * 1024 + d4));
            float4 p1 = __ldcg((const float4*)(g_hprojp2
                        + (size_t)(s * 64 + 32 + b) * 1024 + d4));
            sum[0] += p0.x; sum[0] += p1.x;
            sum[1] += p0.y; sum[1] += p1.y;
            sum[2] += p0.z; sum[2] += p1.z;
            sum[3] += p0.w; sum[3] += p1.w;
        }
        *(float4*)&s_hp[d4] = make_float4(sum[0], sum[1], sum[2], sum[3]);
    }
    __syncthreads();
    for (int l = q * 16 + wd; l < q * 16 + 16; l += 8) {
        const float* xk = x_enc_k + ((size_t)(b * LX + l)) * D;
        float s = 0.f;
#pragma unroll 8
        for (int i = 0; i < 32; i++) {
            int d = lane + i * 32;
            s += fast_tanh(xk[d] + s_hp[d]) * w_att[d];
        }
#pragma unroll
        for (int off = 16; off; off >>= 1) s += __shfl_xor_sync(0xffffffffu, s, off);
        if (lane == 0) {
            float tot = s + w_att_b[0];
            if (xm[b * LX + l]) tot = -1e9f;
            g_wl[b * LX + l] = tot;
        }
    }
}

__device__ void attn_ctx(int bid, float* s_hp, float* s_wl,
                         const float* __restrict__ x_enc) {
    int b = bid >> 2;
    int quarter = bid & 3;
    int tid = threadIdx.x;
    if (tid == 0) {
        float tmp[LX];
        float mx = -1e30f;
        for (int l = 0; l < LX; l++) {
            float v = __ldcg(&g_wl[b * LX + l]);
            tmp[l] = v;
            mx = fmaxf(mx, v);
        }
        float z = 0.f;
        for (int l = 0; l < LX; l++) { float e = expf(tmp[l] - mx); tmp[l] = e; z += e; }
        float inv = 1.f / z;
        for (int l = 0; l < LX; l++) s_wl[l] = tmp[l] * inv;
    }
    __syncthreads();
    {
        int half = tid >> 7;
        int dt = (tid & 127) * 4;
        int d2 = quarter * 512 + dt;
        const float* xe = x_enc + (size_t)b * LX * 2048 + d2;
        float f[4] = {0.f, 0.f, 0.f, 0.f};
        int l0 = half * 32;
#pragma unroll 8
        for (int l = l0; l < l0 + 32; l++) {
            float w = s_wl[l];
            float4 x0 = *(const float4*)(xe + (size_t)l * 2048);
            f[0] += w * x0.x; f[1] += w * x0.y; f[2] += w * x0.z; f[3] += w * x0.w;
        }
        if (half == 0) {
            *(float4*)&s_hp[dt] = make_float4(f[0], f[1], f[2], f[3]);
        }
        __syncthreads();
        if (half == 1) {
            float4 o = *(const float4*)&s_hp[dt];
            f[0] += o.x; f[1] += o.y; f[2] += o.z; f[3] += o.w;
#pragma unroll
            for (int q = 0; q < 4; q++) {
                int dd = 1024 + d2 + q;
                __nv_bfloat16 hi, lo; split_bf(f[q], hi, lo);
                a2st(g_A2p, b, dd, hi);   a2st(g_A2p, b, 3072 + dd, hi);
                a2st(g_A2p, 32 + b, dd, lo);
                a2st(g_A2g, b, dd, hi);   a2st(g_A2g, b, 4096 + dd, hi);
                a2st(g_A2g, 32 + b, dd, lo);
            }
        }
    }
}

// ------------------- persistent step kernel (byte-identical to R12) -------------------
__global__ void __launch_bounds__(256, 1) k_steps(
    const float* __restrict__ x_enc, const float* __restrict__ x_enc_k,
    const unsigned char* __restrict__ xm, const int* __restrict__ y_train,
    const float* __restrict__ word_emb,
    const float* __restrict__ b_ih, const float* __restrict__ b_hh,
    const float* __restrict__ w_trg_b, const float* __restrict__ w_att,
    const float* __restrict__ w_att_b) {
    extern __shared__ __align__(128) char s_ring[];
    __shared__ float s_hp[1024];
    __shared__ float s_wl[LX];
    uint32_t sb = smem_u32(s_ring);
    int bid = blockIdx.x;
    int tid = threadIdx.x;
    unsigned gen = 0, gsc = 0;

    if (tid == 0) { mbar_init1(sb); mbar_init1(sb + 8); mbar_init1(sb + 16); }
    __syncthreads();

    const __nv_bfloat16* Wg = g_Wg2 + (size_t)(bid & 31) * 256 * 4096;
    int g_chunk0 = (bid >> 5) * 64;

    for (int t = 0; t < TT; t++) {
        // phase 1: gates MMA (32 super-chunks)
        if (tid == 0) {
            issue_super(sb, gsc, g_A2g, Wg, g_chunk0);
            issue_super(sb, gsc + 1, g_A2g, Wg, g_chunk0 + 2);
        }
        mma_phase_bulk(sb, gsc, g_A2g, Wg, g_gatesp2, 4096, 32,
                       g_chunk0, (bid & 31) * 128, bid >> 5, true);
        gridbar(++gen);
        // phase 2: LSTM cell + pretanh(t-1) + emb(t+1)
        cell_work(bid, b_ih, b_hh);
        if (t > 0) pretanh_work(t - 1, bid);
        if (bid < 32 && t + 1 < TT) emb_prefetch(bid, t + 1, word_emb, y_train);
        gridbar(++gen);
        // phase 3: hproj MMA (2 super-chunks)
        mma_phase_bulk(sb, gsc, g_A2h,
                       g_Wh2 + (size_t)(bid & 7) * 64 * 4096,
                       g_hprojp2, 1024, 2, (bid >> 3) * 4, (bid & 7) * 128,
                       bid >> 3, false);
        gridbar(++gen);
        // phase 4a: scores
        attn_scores(bid, s_hp, x_enc_k, xm, w_trg_b, w_att, w_att_b);
        gridbar(++gen);
        // phase 4b: softmax + ctx
        attn_ctx(bid, s_hp, s_wl, x_enc);
        gridbar(++gen);
        // phase 5: pre MMA (6 super-chunks, no trailing barrier)
        mma_phase_bulk(sb, gsc, g_A2p,
                       g_Wp2 + (size_t)(bid & 7) * 192 * 4096,
                       g_prep2, 1024, 6, (bid >> 3) * 12, (bid & 7) * 128,
                       bid >> 3, false);
    }
    gridbar(++gen);
    pretanh_work(TT - 1, bid);
}

// ------------------- logits GEMM (R12 tile; dedup k-chunk remap) ------------------------
__global__ void __launch_bounds__(256, 2) k_logits_mma(float* __restrict__ out) {
    __shared__ __align__(16) __nv_bfloat16 sA[2][128][40];
    __shared__ __align__(16) __nv_bfloat16 sB[2][128][40];
    int tid = threadIdx.x;
    int lane = tid & 31, wid = tid >> 5;
    int warpM = wid & 1, warpN = wid >> 1;
    int row0 = blockIdx.x * 128;
    int col0 = blockIdx.y * 128;

    int a_row = (lane & 7) + ((lane >> 3) & 1) * 8;
    int a_k   = (lane >> 4) * 8;
    int b_row = (lane & 7) + (lane >> 4) * 8;
    int b_k   = ((lane >> 3) & 1) * 8;
    uint32_t aBase = smem_u32(&sA[0][0][0]) + (warpM * 64 + a_row) * 80 + a_k * 2;
    uint32_t bBase = smem_u32(&sB[0][0][0]) + (warpN * 32 + b_row) * 80 + b_k * 2;

    int ldr = tid >> 2;
    int ldi = tid & 3;

    float acc[4][4][4];
#pragma unroll
    for (int i = 0; i < 4; i++)
#pragma unroll
        for (int j = 0; j < 4; j++)
#pragma unroll
            for (int q = 0; q < 4; q++) acc[i][j][q] = 0.f;

    // virtual K' = 3072 = [Ahi·Bhi | Alo·Bhi | Ahi·Blo]; chunk remap into dedup storage:
    //   kb_A(i) = (i < 64 ? i : i - 64) * 32    (A = [hi|lo], hi re-read for i>=64)
    //   kb_B(i) = (i < 32 ? i : i - 32) * 32    (B = [hi|lo], hi re-read for 32<=i<64)
#pragma unroll
    for (int q = 0; q < 2; q++) {
        int r = ldr + q * 64;
        cpasync16(smem_u32(&sA[0][r][ldi * 8]), g_Abf + (size_t)(row0 + r) * KPA + ldi * 8);
        cpasync16(smem_u32(&sB[0][r][ldi * 8]), g_Bbf + (size_t)(col0 + r) * KPB + ldi * 8);
    }
    asm volatile("cp.async.commit_group;" ::: "memory");

    const int NCH = 96;
    for (int i = 0; i < NCH; i++) {
        int st = i & 1;
        if (i + 1 < NCH) {
            int ns = st ^ 1;
            int i1 = i + 1;
            int kbA = (i1 < 64 ? i1 : i1 - 64) * 32;
            int kbB = (i1 < 32 ? i1 : i1 - 32) * 32;
#pragma unroll
            for (int q = 0; q < 2; q++) {
                int r = ldr + q * 64;
                cpasync16(smem_u32(&sA[ns][r][ldi * 8]),
                          g_Abf + (size_t)(row0 + r) * KPA + kbA + ldi * 8);
                cpasync16(smem_u32(&sB[ns][r][ldi * 8]),
                          g_Bbf + (size_t)(col0 + r) * KPB + kbB + ldi * 8);
            }
            asm volatile("cp.async.commit_group;" ::: "memory");
            asm volatile("cp.async.wait_group 1;" ::: "memory");
        } else {
            asm volatile("cp.async.wait_group 0;" ::: "memory");
        }
        __syncthreads();

        uint32_t stoff = st * (uint32_t)(128 * 80);
#pragma unroll
        for (int k16 = 0; k16 < 2; k16++) {
            uint32_t koff = stoff + k16 * 32;
            uint32_t a[4][4], b[2][4];
#pragma unroll
            for (int mt = 0; mt < 4; mt++) ldm_x4(a[mt], aBase + koff + mt * 1280);
#pragma unroll
            for (int p = 0; p < 2; p++)    ldm_x4(b[p], bBase + koff + p * 1280);
#pragma unroll
            for (int mt = 0; mt < 4; mt++)
#pragma unroll
                for (int nt = 0; nt < 4; nt++)
                    mma_bf16(acc[mt][nt], a[mt], &b[nt >> 1][(nt & 1) * 2]);
        }
        __syncthreads();
    }

    int grp = lane >> 2, tig = lane & 3;
#pragma unroll
    for (int mt = 0; mt < 4; mt++) {
        int m1 = row0 + warpM * 64 + mt * 16 + grp;
        int m2 = m1 + 8;
        float* o1 = out + ((size_t)(m1 & 31) * TT + (m1 >> 5)) * V;
        float* o2 = out + ((size_t)(m2 & 31) * TT + (m2 >> 5)) * V;
#pragma unroll
        for (int nt = 0; nt < 4; nt++) {
            int n = col0 + warpN * 32 + nt * 8 + tig * 2;
            *(float2*)(o1 + n) = make_float2(acc[mt][nt][0], acc[mt][nt][1]);
            *(float2*)(o2 + n) = make_float2(acc[mt][nt][2], acc[mt][nt][3]);
        }
    }
}

// ------------------- launch ---------------------------------------------------------------
extern "C" void kernel_launch(void* const* d_in, const int* in_sizes, int n_in,
                              void* d_out, int out_size) {
    const float* x_enc      = (const float*)d_in[0];
    const float* x_enc_k    = (const float*)d_in[1];
    const float* h0         = (const float*)d_in[2];
    const float* c0         = (const float*)d_in[3];
    const unsigned char* xm = (const unsigned char*)d_in[4];
    const int*   y_train    = (const int*)d_in[5];
    const float* word_emb   = (const float*)d_in[6];
    const float* W_ih       = (const float*)d_in[7];
    const float* W_hh       = (const float*)d_in[8];
    const float* b_ih       = (const float*)d_in[9];
    const float* b_hh       = (const float*)d_in[10];
    const float* w_trg_W    = (const float*)d_in[11];
    const float* w_trg_b    = (const float*)d_in[12];
    const float* w_att      = (const float*)d_in[13];
    const float* w_att_b    = (const float*)d_in[14];
    const float* ctx_W      = (const float*)d_in[15];
    const float* RW         = (const float*)d_in[16];
    float* out = (float*)d_out;

    cudaFuncSetAttribute(k_steps, cudaFuncAttributeMaxDynamicSharedMemorySize, STEPS_DYN);

    k_convB<<<(V * D) / 256, 256>>>(RW);
    k_convWg<<<dim3(16, 4096), 256>>>(W_ih, W_hh);
    k_convWh<<<dim3(4, 1024), 256>>>(w_trg_W);
    k_convWp<<<dim3(12, 1024), 256>>>(ctx_W);
    int init_total = 64 * 8192 + 32 * 1024 + 32 * 3072 + B * D;
    k_init0<<<(init_total + 255) / 256, 256>>>(h0, c0, word_emb, y_train);
    k_steps<<<GRIDN, 256, STEPS_DYN>>>(x_enc, x_enc_k, xm, y_train, word_emb,
                                       b_ih, b_hh, w_trg_b, w_att, w_att_b);
    k_logits_mma<<<dim3((B * TT) / 128, V / 128), 256>>>(out);
}

// round 15
// speedup vs baseline: 1.0901x; 1.0425x over previous
#include <cuda_runtime.h>
#include <cuda_bf16.h>
#include <math.h>
#include <stdint.h>

#define B  32
#define LX 64
#define TT 64
#define D  1024
#define V  32000
#define KPA 2048        // dedup A': [hi|lo]
#define KPB 2048        // dedup B': [hi|lo]
#define GRIDN 128
// dynamic ring for k_steps: mbar@0 (32B) | A stages 3x8192 @32 | B stages 3x16384 @24608
#define SC_ABASE 32
#define SC_BBASE 24608
#define STEPS_DYN (32 + 3 * 8192 + 3 * 16384)

// ------------------- device globals --------------------------------------------
__device__ float g_c[B * D];
__device__ float g_gatesp2[4 * 64 * 4096];
__device__ float g_hprojp2[16 * 64 * 1024];
__device__ float g_prep2[16 * 64 * 1024];
__device__ float g_wl[B * LX];
// step-GEMM A operands, chunk-block layout [chunk][64][32] (4KB blocks)
__device__ __align__(16) __nv_bfloat16 g_A2g[256 * 64 * 32];
__device__ __align__(16) __nv_bfloat16 g_A2h[64 * 64 * 32];
__device__ __align__(16) __nv_bfloat16 g_A2p[192 * 64 * 32];
// logits operands (row-major, dedup [hi|lo])
__device__ __align__(16) __nv_bfloat16 g_Abf[(TT * B) * KPA];
__device__ __align__(16) __nv_bfloat16 g_Bbf[(size_t)V * KPB];
// weights, chunk-block layout [coltile][chunk][128][32] (8KB blocks)
__device__ __align__(16) __nv_bfloat16 g_Wg2[(size_t)32 * 256 * 128 * 32];
__device__ __align__(16) __nv_bfloat16 g_Wh2[8 * 64 * 128 * 32];
__device__ __align__(16) __nv_bfloat16 g_Wp2[8 * 192 * 128 * 32];
__device__ int g_flags[GRIDN];

// ------------------- helpers -----------------------------------------------------
__device__ __forceinline__ float fast_tanh(float x) {
    float e = __expf(2.f * x);
    return 1.f - __fdividef(2.f, e + 1.f);
}
__device__ __forceinline__ uint32_t smem_u32(const void* p) {
    uint32_t a;
    asm("{ .reg .u64 t; cvta.to.shared.u64 t, %1; cvt.u32.u64 %0, t; }" : "=r"(a) : "l"(p));
    return a;
}
__device__ __forceinline__ void cpasync16(uint32_t dst, const void* src) {
    asm volatile("cp.async.cg.shared.global [%0], [%1], 16;" :: "r"(dst), "l"(src));
}
__device__ __forceinline__ void ldm_x4(uint32_t* r, uint32_t addr) {
    asm volatile("ldmatrix.sync.aligned.m8n8.x4.shared.b16 {%0,%1,%2,%3}, [%4];"
        : "=r"(r[0]), "=r"(r[1]), "=r"(r[2]), "=r"(r[3]) : "r"(addr));
}
__device__ __forceinline__ void mma_bf16(float* c, const uint32_t* a, const uint32_t* b) {
    asm volatile("mma.sync.aligned.m16n8k16.row.col.f32.bf16.bf16.f32 "
        "{%0,%1,%2,%3}, {%4,%5,%6,%7}, {%8,%9}, {%0,%1,%2,%3};"
        : "+f"(c[0]), "+f"(c[1]), "+f"(c[2]), "+f"(c[3])
        : "r"(a[0]), "r"(a[1]), "r"(a[2]), "r"(a[3]), "r"(b[0]), "r"(b[1]));
}
__device__ __forceinline__ void split_bf(float v, __nv_bfloat16& hi, __nv_bfloat16& lo) {
    hi = __float2bfloat16_rn(v);
    lo = __float2bfloat16_rn(v - __bfloat162float(hi));
}
__device__ __forceinline__ uint32_t pk2(__nv_bfloat16 a, __nv_bfloat16 b) {
    __nv_bfloat162 t; t.x = a; t.y = b;
    return *(uint32_t*)&t;
}
__device__ __forceinline__ int swoff(int row, int kin) {
    return ((((kin >> 3) ^ ((row >> 1) & 3)) << 3) | (kin & 7));
}
// scalar store (init only)
__device__ __forceinline__ void a2st(__nv_bfloat16* base, int row, int k, __nv_bfloat16 v) {
    base[((k >> 5) * 64 + row) * 32 + swoff(row, k & 31)] = v;
}
// vector store: 4 consecutive k (k 4-aligned) -> one 8B store
__device__ __forceinline__ void a2st4(__nv_bfloat16* base, int row, int k,
                                      const __nv_bfloat16* h) {
    int off = ((k >> 5) * 64 + row) * 32
            + ((((k >> 3) & 3) ^ ((row >> 1) & 3)) << 3) + (k & 7);
    *(uint2*)(base + off) = make_uint2(pk2(h[0], h[1]), pk2(h[2], h[3]));
}
// vector store: 8 consecutive k (k 8-aligned) -> one 16B store
__device__ __forceinline__ void w2st8(__nv_bfloat16* base, int nch, int j, int k,
                                      const __nv_bfloat16* h) {
    size_t off = ((size_t)((j >> 7) * nch + (k >> 5)) * 128 + (j & 127)) * 32
               + ((((k >> 3) & 3) ^ (((j & 127) >> 1) & 3)) << 3);
    *(uint4*)(base + off) = make_uint4(pk2(h[0], h[1]), pk2(h[2], h[3]),
                                       pk2(h[4], h[5]), pk2(h[6], h[7]));
}
// split 8 floats into hi/lo arrays
__device__ __forceinline__ void split8(const float* v, __nv_bfloat16* hi, __nv_bfloat16* lo) {
#pragma unroll
    for (int q = 0; q < 8; q++) split_bf(v[q], hi[q], lo[q]);
}
// ------------------- bulk copy + mbarrier ------------------------------------------
__device__ __forceinline__ void bulk_g2s(uint32_t dst, const void* src, uint32_t bytes,
                                         uint32_t mbar) {
    asm volatile(
        "cp.async.bulk.shared::cluster.global.mbarrier::complete_tx::bytes [%0], [%1], %2, [%3];"
        :: "r"(dst), "l"(src), "r"(bytes), "r"(mbar) : "memory");
}
__device__ __forceinline__ void mbar_expect(uint32_t mbar, uint32_t bytes) {
    asm volatile("mbarrier.arrive.expect_tx.shared.b64 _, [%0], %1;"
                 :: "r"(mbar), "r"(bytes) : "memory");
}
__device__ __forceinline__ void mbar_init1(uint32_t mbar) {
    asm volatile("mbarrier.init.shared.b64 [%0], 1;" :: "r"(mbar) : "memory");
}
__device__ __forceinline__ void mbar_wait(uint32_t mbar, uint32_t parity) {
    asm volatile(
        "{\n\t.reg .pred P;\n"
        "W%=:\n\t"
        "mbarrier.try_wait.parity.shared.b64 P, [%0], %1;\n\t"
        "@P bra D%=;\n\t"
        "bra W%=;\n"
        "D%=:\n\t}"
        :: "r"(mbar), "r"(parity) : "memory");
}
// issue one SUPER-chunk (two contiguous 32-k blocks) into ring stage idx%3
__device__ __forceinline__ void issue_super(uint32_t sb, unsigned idx,
        const __nv_bfloat16* __restrict__ Ablk,
        const __nv_bfloat16* __restrict__ Bblk, int chunk) {
    uint32_t st = idx % 3u, mb = sb + st * 8u;
    mbar_expect(mb, 24576u);
    bulk_g2s(sb + SC_ABASE + st * 8192u, Ablk + (size_t)chunk * 2048, 8192u, mb);
    bulk_g2s(sb + SC_BBASE + st * 16384u, Bblk + (size_t)chunk * 4096, 16384u, mb);
}
// ------------------- flag-array grid barrier -----------------------------------------
__device__ __forceinline__ void gridbar(unsigned gen) {
    asm volatile("fence.proxy.async;" ::: "memory");
    __threadfence();
    __syncthreads();
    if (threadIdx.x == 0) atomicExch(&g_flags[blockIdx.x], (int)gen);
    bool ok;
    do {
        ok = (threadIdx.x >= GRIDN) ||
             (__ldcg(&g_flags[threadIdx.x]) >= (int)gen);
    } while (!__syncthreads_and(ok));
}

// ------------------- init -----------------------------------------------------------
__global__ void k_init0(const float* __restrict__ h0, const float* __restrict__ c0,
                        const float* __restrict__ word_emb,
                        const int* __restrict__ y_train) {
    int i = blockIdx.x * 256 + threadIdx.x;
    if (i < GRIDN) g_flags[i] = 0;
    if (i < 64 * 8192) {                 // gates A2 for t=0
        int r = i >> 13, k = i & 8191;
        int b = r & 31;
        bool isLo = r >= 32;
        int ks = (k < 4096) ? k : k - 4096;
        float v = 0.f;
        bool zero = (isLo && k >= 4096);
        if (!zero) {
            if (ks < 1024) {
                int y = y_train[b * TT + 0];
                v = word_emb[(size_t)y * D + ks];
            } else if (ks < 3072) {
                v = 0.f;
            } else {
                v = h0[b * D + (ks - 3072)];
            }
        }
        __nv_bfloat16 hi, lo; split_bf(v, hi, lo);
        a2st(g_A2g, r, k, zero ? __float2bfloat16_rn(0.f) : (isLo ? lo : hi));
        return;
    }
    int j = i - 64 * 8192;
    if (j < 32 * 1024) {
        int r = 32 + (j >> 10), k = 1024 + (j & 1023);
        a2st(g_A2h, r, k, __float2bfloat16_rn(0.f));
        return;
    }
    j -= 32 * 1024;
    if (j < 32 * 3072) {
        int r = 32 + j / 3072, k = 3072 + j % 3072;
        a2st(g_A2p, r, k, __float2bfloat16_rn(0.f));
        return;
    }
    j -= 32 * 3072;
    if (j < B * D) g_c[j] = c0[j];
}

// ------------------- weight conversions (vectorized 8k/thread) -----------------------
__global__ void k_convB(const float* __restrict__ RW) {
    int i = blockIdx.x * 256 + threadIdx.x;          // < V*128
    int r = i >> 7, d = (i & 127) * 8;
    float4 v0 = *(const float4*)(RW + (size_t)r * D + d);
    float4 v1 = *(const float4*)(RW + (size_t)r * D + d + 4);
    float v[8] = {v0.x, v0.y, v0.z, v0.w, v1.x, v1.y, v1.z, v1.w};
    __nv_bfloat16 hi[8], lo[8];
    split8(v, hi, lo);
    __nv_bfloat16* row = g_Bbf + (size_t)r * KPB;
    *(uint4*)(row + d) = make_uint4(pk2(hi[0], hi[1]), pk2(hi[2], hi[3]),
                                    pk2(hi[4], hi[5]), pk2(hi[6], hi[7]));
    *(uint4*)(row + 1024 + d) = make_uint4(pk2(lo[0], lo[1]), pk2(lo[2], lo[3]),
                                           pk2(lo[4], lo[5]), pk2(lo[6], lo[7]));
}
__global__ void k_convWg(const float* __restrict__ Wih, const float* __restrict__ Whh) {
    int kg = blockIdx.x * 256 + threadIdx.x;         // 0..511
    int j = blockIdx.y;
    int k = kg * 8;
    const float* src = (k < 3072) ? Wih + (size_t)j * 3072 + k
                                  : Whh + (size_t)j * 1024 + (k - 3072);
    float4 v0 = *(const float4*)src;
    float4 v1 = *(const float4*)(src + 4);
    float v[8] = {v0.x, v0.y, v0.z, v0.w, v1.x, v1.y, v1.z, v1.w};
    __nv_bfloat16 hi[8], lo[8];
    split8(v, hi, lo);
    w2st8(g_Wg2, 256, j, k, hi);
    w2st8(g_Wg2, 256, j, 4096 + k, lo);
}
__global__ void k_convWh(const float* __restrict__ Wt) {
    int kg = threadIdx.x;                            // 0..127
    int j = blockIdx.x;
    int k = kg * 8;
    float4 v0 = *(const float4*)(Wt + (size_t)j * 1024 + k);
    float4 v1 = *(const float4*)(Wt + (size_t)j * 1024 + k + 4);
    float v[8] = {v0.x, v0.y, v0.z, v0.w, v1.x, v1.y, v1.z, v1.w};
    __nv_bfloat16 hi[8], lo[8];
    split8(v, hi, lo);
    w2st8(g_Wh2, 64, j, k, hi);
    w2st8(g_Wh2, 64, j, 1024 + k, lo);
}
__global__ void k_convWp(const float* __restrict__ Cw) {
    int kg = blockIdx.x * 192 + threadIdx.x;         // 0..383
    int j = blockIdx.y;
    int k = kg * 8;
    float4 v0 = *(const float4*)(Cw + (size_t)j * 3072 + k);
    float4 v1 = *(const float4*)(Cw + (size_t)j * 3072 + k + 4);
    float v[8] = {v0.x, v0.y, v0.z, v0.w, v1.x, v1.y, v1.z, v1.w};
    __nv_bfloat16 hi[8], lo[8];
    split8(v, hi, lo);
    w2st8(g_Wp2, 192, j, k, hi);
    w2st8(g_Wp2, 192, j, 3072 + k, lo);
}

// ------------------- super-chunk 64xK @ Kx128 MMA phase -------------------------------
__device__ void mma_phase_bulk(uint32_t sb, unsigned& gsc,
        const __nv_bfloat16* __restrict__ Ablk,
        const __nv_bfloat16* __restrict__ Bblk,
        float* __restrict__ part, int ncols,
        int nsuper, int chunk0, int col0, int split, bool pre_issued) {
    int tid = threadIdx.x;
    int lane = tid & 31, wid = tid >> 5;
    int warpM = wid & 1, warpN = wid >> 1;

    int a_row = (lane & 7) + ((lane >> 3) & 1) * 8;
    int ca0 = lane >> 4;
    int b_row = (lane & 7) + (lane >> 4) * 8;
    int cb0 = (lane >> 3) & 1;
    int rA[2], sA_[2], rB[2], sB_[2];
#pragma unroll
    for (int mt = 0; mt < 2; mt++) {
        int r = warpM * 32 + mt * 16 + a_row;
        rA[mt] = r * 64; sA_[mt] = (r >> 1) & 3;
    }
#pragma unroll
    for (int p = 0; p < 2; p++) {
        int r = warpN * 32 + p * 16 + b_row;
        rB[p] = r * 64; sB_[p] = (r >> 1) & 3;
    }

    float acc[2][4][4] = {};

    if (!pre_issued && tid == 0) {
        issue_super(sb, gsc, Ablk, Bblk, chunk0);
        if (nsuper > 1) issue_super(sb, gsc + 1, Ablk, Bblk, chunk0 + 2);
    }
    for (int i = 0; i < nsuper; i++) {
        if (i + 2 < nsuper && tid == 0)
            issue_super(sb, gsc + (unsigned)(i + 2), Ablk, Bblk, chunk0 + 2 * (i + 2));
        unsigned idx = gsc + (unsigned)i;
        uint32_t st = idx % 3u;
        mbar_wait(sb + st * 8u, (idx / 3u) & 1u);
#pragma unroll
        for (int sub = 0; sub < 2; sub++) {
            uint32_t aOff = sb + SC_ABASE + st * 8192u + sub * 4096u;
            uint32_t bOff = sb + SC_BBASE + st * 16384u + sub * 8192u;
#pragma unroll
            for (int k16 = 0; k16 < 2; k16++) {
                int ca = ca0 + 2 * k16, cb = cb0 + 2 * k16;
                uint32_t a0[4], a1[4], bb[2][4];
                ldm_x4(a0, aOff + rA[0] + ((ca ^ sA_[0]) << 4));
                ldm_x4(a1, aOff + rA[1] + ((ca ^ sA_[1]) << 4));
                ldm_x4(bb[0], bOff + rB[0] + ((cb ^ sB_[0]) << 4));
                ldm_x4(bb[1], bOff + rB[1] + ((cb ^ sB_[1]) << 4));
#pragma unroll
                for (int nt = 0; nt < 4; nt++) {
                    mma_bf16(acc[0][nt], a0, &bb[nt >> 1][(nt & 1) * 2]);
                    mma_bf16(acc[1][nt], a1, &bb[nt >> 1][(nt & 1) * 2]);
                }
            }
        }
        __syncthreads();
    }
    gsc += (unsigned)nsuper;

    int grp = lane >> 2, tig = lane & 3;
#pragma unroll
    for (int mt = 0; mt < 2; mt++) {
        int m1 = warpM * 32 + mt * 16 + grp;
        int m2 = m1 + 8;
        float* p1 = part + (size_t)(split * 64 + m1) * ncols + col0 + warpN * 32;
        float* p2 = part + (size_t)(split * 64 + m2) * ncols + col0 + warpN * 32;
#pragma unroll
        for (int nt = 0; nt < 4; nt++) {
            int n = nt * 8 + tig * 2;
            *(float2*)(p1 + n) = make_float2(acc[mt][nt][0], acc[mt][nt][1]);
            *(float2*)(p2 + n) = make_float2(acc[mt][nt][2], acc[mt][nt][3]);
        }
    }
}

// ------------------- scalar phase work ------------------------------------------------
__device__ void emb_prefetch(int b, int tnext, const float* __restrict__ word_emb,
                             const int* __restrict__ y_train) {
    int d = threadIdx.x * 4;
    int y = y_train[b * TT + tnext];
    float4 v = *(const float4*)(word_emb + (size_t)y * D + d);
    float vv[4] = {v.x, v.y, v.z, v.w};
    __nv_bfloat16 hi[4], lo[4];
#pragma unroll
    for (int q = 0; q < 4; q++) split_bf(vv[q], hi[q], lo[q]);
    a2st4(g_A2g, b, d, hi);
    a2st4(g_A2g, b, 4096 + d, hi);
    a2st4(g_A2g, 32 + b, d, lo);
}

__device__ void cell_work(int bid, const float* __restrict__ b_ih,
                          const float* __restrict__ b_hh) {
    int tid = threadIdx.x;
    if (tid >= 64) return;
    int m = bid >> 2;
    int d = (bid & 3) * 256 + tid * 4;
    int id = m * 1024 + d;
    float gv[4][4];
#pragma unroll
    for (int g = 0; g < 4; g++) {
        float4 bi = *(const float4*)(b_ih + g * 1024 + d);
        float4 bh = *(const float4*)(b_hh + g * 1024 + d);
        gv[g][0] = bi.x + bh.x; gv[g][1] = bi.y + bh.y;
        gv[g][2] = bi.z + bh.z; gv[g][3] = bi.w + bh.w;
    }
#pragma unroll
    for (int s = 0; s < 4; s++) {
#pragma unroll
        for (int g = 0; g < 4; g++) {
            float4 p0 = __ldcg((const float4*)(g_gatesp2
                         + (size_t)(s * 64 + m) * 4096 + g * 1024 + d));
            float4 p1 = __ldcg((const float4*)(g_gatesp2
                         + (size_t)(s * 64 + 32 + m) * 4096 + g * 1024 + d));
            gv[g][0] += p0.x; gv[g][0] += p1.x;
            gv[g][1] += p0.y; gv[g][1] += p1.y;
            gv[g][2] += p0.z; gv[g][2] += p1.z;
            gv[g][3] += p0.w; gv[g][3] += p1.w;
        }
    }
    float4 cold = __ldcg((const float4*)&g_c[id]);
    float co[4] = {cold.x, cold.y, cold.z, cold.w};
    float4 cnew;
    float* cn = (float*)&cnew;
    __nv_bfloat16 hh[4], hl[4];
#pragma unroll
    for (int q = 0; q < 4; q++) {
        float si = 1.f / (1.f + expf(-gv[0][q]));
        float sf = 1.f / (1.f + expf(-gv[1][q]));
        float so = 1.f / (1.f + expf(-gv[3][q]));
        float c = sf * co[q] + si * tanhf(gv[2][q]);
        cn[q] = c;
        float h = so * tanhf(c);
        split_bf(h, hh[q], hl[q]);
    }
    a2st4(g_A2h, m, d, hh);        a2st4(g_A2h, m, 1024 + d, hh);
    a2st4(g_A2h, 32 + m, d, hl);
    a2st4(g_A2p, m, d, hh);        a2st4(g_A2p, m, 3072 + d, hh);
    a2st4(g_A2p, 32 + m, d, hl);
    a2st4(g_A2g, m, 3072 + d, hh); a2st4(g_A2g, m, 7168 + d, hh);
    a2st4(g_A2g, 32 + m, 3072 + d, hl);
    *(float4*)&g_c[id] = cnew;
}

__device__ void pretanh_work(int t, int bid) {
    int tid = threadIdx.x;
    if (tid >= 64) return;
    int m = bid >> 2;
    int d = (bid & 3) * 256 + tid * 4;
    float v[4] = {0.f, 0.f, 0.f, 0.f};
#pragma unroll
    for (int s = 0; s < 16; s++) {
        float4 p0 = __ldcg((const float4*)(g_prep2 + (size_t)(s * 64 + m) * 1024 + d));
        float4 p1 = __ldcg((const float4*)(g_prep2 + (size_t)(s * 64 + 32 + m) * 1024 + d));
        v[0] += p0.x; v[0] += p1.x;
        v[1] += p0.y; v[1] += p1.y;
        v[2] += p0.z; v[2] += p1.z;
        v[3] += p0.w; v[3] += p1.w;
    }
    int row = t * B + m;
    __nv_bfloat16* arow = g_Abf + (size_t)row * KPA;
    __nv_bfloat16 hi[4], lo[4];
#pragma unroll
    for (int q = 0; q < 4; q++) {
        float tv = tanhf(v[q]);
        split_bf(tv, hi[q], lo[q]);
    }
    *(uint2*)(arow + d)        = make_uint2(pk2(hi[0], hi[1]), pk2(hi[2], hi[3]));
    *(uint2*)(arow + 1024 + d) = make_uint2(pk2(lo[0], lo[1]), pk2(lo[2], lo[3]));
}

__device__ void attn_scores(int bid, float* s_hp,
                            const float* __restrict__ x_enc_k,
                            const unsigned char* __restrict__ xm,
                            const float* __restrict__ w_trg_b,
                            const float* __restrict__ w_att,
                            const float* __restrict__ w_att_b) {
    int b = bid >> 2;
    int q = bid & 3;
    int tid = threadIdx.x;
    int lane = tid & 31, wd = tid >> 5;
    {
        int d4 = tid * 4;
        float4 bi = *(const float4*)(w_trg_b + d4);
        float sum[4] = {bi.x, bi.y, bi.z, bi.w};
#pragma unroll
        for (int s = 0; s < 16; s++) {
            float4 p0 = __ldcg((const float4*)(g_hprojp2
                        + (size_t)(s * 64 + b) * 1024 + d4));
            float4 p1 = __ldcg((const float4*)(g_hprojp2
                        + (size_t)(s * 64 + 32 + b) * 1024 + d4));
            sum[0] += p0.x; sum[0] += p1.x;
            sum[1] += p0.y; sum[1] += p1.y;
            sum[2] += p0.z; sum[2] += p1.z;
            sum[3] += p0.w; sum[3] += p1.w;
        }
        *(float4*)&s_hp[d4] = make_float4(sum[0], sum[1], sum[2], sum[3]);
    }
    __syncthreads();
    for (int l = q * 16 + wd; l < q * 16 + 16; l += 8) {
        const float* xk = x_enc_k + ((size_t)(b * LX + l)) * D;
        float s = 0.f;
#pragma unroll 8
        for (int i = 0; i < 32; i++) {
            int d = lane + i * 32;
            s += fast_tanh(xk[d] + s_hp[d]) * w_att[d];
        }
#pragma unroll
        for (int off = 16; off; off >>= 1) s += __shfl_xor_sync(0xffffffffu, s, off);
        if (lane == 0) {
            float tot = s + w_att_b[0];
            if (xm[b * LX + l]) tot = -1e9f;
            g_wl[b * LX + l] = tot;
        }
    }
}

__device__ void attn_ctx(int bid, float* s_hp, float* s_wl,
                         const float* __restrict__ x_enc) {
    int b = bid >> 2;
    int quarter = bid & 3;
    int tid = threadIdx.x;
    if (tid == 0) {
        float tmp[LX];
        float mx = -1e30f;
        for (int l = 0; l < LX; l++) {
            float v = __ldcg(&g_wl[b * LX + l]);
            tmp[l] = v;
            mx = fmaxf(mx, v);
        }
        float z = 0.f;
        for (int l = 0; l < LX; l++) { float e = expf(tmp[l] - mx); tmp[l] = e; z += e; }
        float inv = 1.f / z;
        for (int l = 0; l < LX; l++) s_wl[l] = tmp[l] * inv;
    }
    __syncthreads();
    {
        int half = tid >> 7;
        int dt = (tid & 127) * 4;
        int d2 = quarter * 512 + dt;
        const float* xe = x_enc + (size_t)b * LX * 2048 + d2;
        float f[4] = {0.f, 0.f, 0.f, 0.f};
        int l0 = half * 32;
#pragma unroll 8
        for (int l = l0; l < l0 + 32; l++) {
            float w = s_wl[l];
            float4 x0 = *(const float4*)(xe + (size_t)l * 2048);
            f[0] += w * x0.x; f[1] += w * x0.y; f[2] += w * x0.z; f[3] += w * x0.w;
        }
        if (half == 0) {
            *(float4*)&s_hp[dt] = make_float4(f[0], f[1], f[2], f[3]);
        }
        __syncthreads();
        if (half == 1) {
            float4 o = *(const float4*)&s_hp[dt];
            f[0] += o.x; f[1] += o.y; f[2] += o.z; f[3] += o.w;
            int dd = 1024 + d2;
            __nv_bfloat16 hi[4], lo[4];
#pragma unroll
            for (int q = 0; q < 4; q++) split_bf(f[q], hi[q], lo[q]);
            a2st4(g_A2p, b, dd, hi);        a2st4(g_A2p, b, 3072 + dd, hi);
            a2st4(g_A2p, 32 + b, dd, lo);
            a2st4(g_A2g, b, dd, hi);        a2st4(g_A2g, b, 4096 + dd, hi);
            a2st4(g_A2g, 32 + b, dd, lo);
        }
    }
}

// ------------------- persistent step kernel (structure identical to R12/R14) ----------
__global__ void __launch_bounds__(256, 1) k_steps(
    const float* __restrict__ x_enc, const float* __restrict__ x_enc_k,
    const unsigned char* __restrict__ xm, const int* __restrict__ y_train,
    const float* __restrict__ word_emb,
    const float* __restrict__ b_ih, const float* __restrict__ b_hh,
    const float* __restrict__ w_trg_b, const float* __restrict__ w_att,
    const float* __restrict__ w_att_b) {
    extern __shared__ __align__(128) char s_ring[];
    __shared__ float s_hp[1024];
    __shared__ float s_wl[LX];
    uint32_t sb = smem_u32(s_ring);
    int bid = blockIdx.x;
    int tid = threadIdx.x;
    unsigned gen = 0, gsc = 0;

    if (tid == 0) { mbar_init1(sb); mbar_init1(sb + 8); mbar_init1(sb + 16); }
    __syncthreads();

    const __nv_bfloat16* Wg = g_Wg2 + (size_t)(bid & 31) * 256 * 4096;
    int g_chunk0 = (bid >> 5) * 64;

    for (int t = 0; t < TT; t++) {
        // phase 1: gates MMA (32 super-chunks)
        if (tid == 0) {
            issue_super(sb, gsc, g_A2g, Wg, g_chunk0);
            issue_super(sb, gsc + 1, g_A2g, Wg, g_chunk0 + 2);
        }
        mma_phase_bulk(sb, gsc, g_A2g, Wg, g_gatesp2, 4096, 32,
                       g_chunk0, (bid & 31) * 128, bid >> 5, true);
        gridbar(++gen);
        // phase 2: LSTM cell + pretanh(t-1) + emb(t+1)
        cell_work(bid, b_ih, b_hh);
        if (t > 0) pretanh_work(t - 1, bid);
        if (bid < 32 && t + 1 < TT) emb_prefetch(bid, t + 1, word_emb, y_train);
        gridbar(++gen);
        // phase 3: hproj MMA (2 super-chunks)
        mma_phase_bulk(sb, gsc, g_A2h,
                       g_Wh2 + (size_t)(bid & 7) * 64 * 4096,
                       g_hprojp2, 1024, 2, (bid >> 3) * 4, (bid & 7) * 128,
                       bid >> 3, false);
        gridbar(++gen);
        // phase 4a: scores
        attn_scores(bid, s_hp, x_enc_k, xm, w_trg_b, w_att, w_att_b);
        gridbar(++gen);
        // phase 4b: softmax + ctx
        attn_ctx(bid, s_hp, s_wl, x_enc);
        gridbar(++gen);
        // phase 5: pre MMA (6 super-chunks, no trailing barrier)
        mma_phase_bulk(sb, gsc, g_A2p,
                       g_Wp2 + (size_t)(bid & 7) * 192 * 4096,
                       g_prep2, 1024, 6, (bid >> 3) * 12, (bid & 7) * 128,
                       bid >> 3, false);
    }
    gridbar(++gen);
    pretanh_work(TT - 1, bid);
}

// ------------------- logits GEMM (R14, known passing) -----------------------------------
__global__ void __launch_bounds__(256, 2) k_logits_mma(float* __restrict__ out) {
    __shared__ __align__(16) __nv_bfloat16 sA[2][128][40];
    __shared__ __align__(16) __nv_bfloat16 sB[2][128][40];
    int tid = threadIdx.x;
    int lane = tid & 31, wid = tid >> 5;
    int warpM = wid & 1, warpN = wid >> 1;
    int row0 = blockIdx.x * 128;
    int col0 = blockIdx.y * 128;

    int a_row = (lane & 7) + ((lane >> 3) & 1) * 8;
    int a_k   = (lane >> 4) * 8;
    int b_row = (lane & 7) + (lane >> 4) * 8;
    int b_k   = ((lane >> 3) & 1) * 8;
    uint32_t aBase = smem_u32(&sA[0][0][0]) + (warpM * 64 + a_row) * 80 + a_k * 2;
    uint32_t bBase = smem_u32(&sB[0][0][0]) + (warpN * 32 + b_row) * 80 + b_k * 2;

    int ldr = tid >> 2;
    int ldi = tid & 3;

    float acc[4][4][4];
#pragma unroll
    for (int i = 0; i < 4; i++)
#pragma unroll
        for (int j = 0; j < 4; j++)
#pragma unroll
            for (int q = 0; q < 4; q++) acc[i][j][q] = 0.f;

#pragma unroll
    for (int q = 0; q < 2; q++) {
        int r = ldr + q * 64;
        cpasync16(smem_u32(&sA[0][r][ldi * 8]), g_Abf + (size_t)(row0 + r) * KPA + ldi * 8);
        cpasync16(smem_u32(&sB[0][r][ldi * 8]), g_Bbf + (size_t)(col0 + r) * KPB + ldi * 8);
    }
    asm volatile("cp.async.commit_group;" ::: "memory");

    const int NCH = 96;
    for (int i = 0; i < NCH; i++) {
        int st = i & 1;
        if (i + 1 < NCH) {
            int ns = st ^ 1;
            int i1 = i + 1;
            int kbA = (i1 < 64 ? i1 : i1 - 64) * 32;
            int kbB = (i1 < 32 ? i1 : i1 - 32) * 32;
#pragma unroll
            for (int q = 0; q < 2; q++) {
                int r = ldr + q * 64;
                cpasync16(smem_u32(&sA[ns][r][ldi * 8]),
                          g_Abf + (size_t)(row0 + r) * KPA + kbA + ldi * 8);
                cpasync16(smem_u32(&sB[ns][r][ldi * 8]),
                          g_Bbf + (size_t)(col0 + r) * KPB + kbB + ldi * 8);
            }
            asm volatile("cp.async.commit_group;" ::: "memory");
            asm volatile("cp.async.wait_group 1;" ::: "memory");
        } else {
            asm volatile("cp.async.wait_group 0;" ::: "memory");
        }
        __syncthreads();

        uint32_t stoff = st * (uint32_t)(128 * 80);
#pragma unroll
        for (int k16 = 0; k16 < 2; k16++) {
            uint32_t koff = stoff + k16 * 32;
            uint32_t a[4][4], b[2][4];
#pragma unroll
            for (int mt = 0; mt < 4; mt++) ldm_x4(a[mt], aBase + koff + mt * 1280);
#pragma unroll
            for (int p = 0; p < 2; p++)    ldm_x4(b[p], bBase + koff + p * 1280);
#pragma unroll
            for (int mt = 0; mt < 4; mt++)
#pragma unroll
                for (int nt = 0; nt < 4; nt++)
                    mma_bf16(acc[mt][nt], a[mt], &b[nt >> 1][(nt & 1) * 2]);
        }
        __syncthreads();
    }

    int grp = lane >> 2, tig = lane & 3;
#pragma unroll
    for (int mt = 0; mt < 4; mt++) {
        int m1 = row0 + warpM * 64 + mt * 16 + grp;
        int m2 = m1 + 8;
        float* o1 = out + ((size_t)(m1 & 31) * TT + (m1 >> 5)) * V;
        float* o2 = out + ((size_t)(m2 & 31) * TT + (m2 >> 5)) * V;
#pragma unroll
        for (int nt = 0; nt < 4; nt++) {
            int n = col0 + warpN * 32 + nt * 8 + tig * 2;
            *(float2*)(o1 + n) = make_float2(acc[mt][nt][0], acc[mt][nt][1]);
            *(float2*)(o2 + n) = make_float2(acc[mt][nt][2], acc[mt][nt][3]);
        }
    }
}

// ------------------- launch ---------------------------------------------------------------
extern "C" void kernel_launch(void* const* d_in, const int* in_sizes, int n_in,
                              void* d_out, int out_size) {
    const float* x_enc      = (const float*)d_in[0];
    const float* x_enc_k    = (const float*)d_in[1];
    const float* h0         = (const float*)d_in[2];
    const float* c0         = (const float*)d_in[3];
    const unsigned char* xm = (const unsigned char*)d_in[4];
    const int*   y_train    = (const int*)d_in[5];
    const float* word_emb   = (const float*)d_in[6];
    const float* W_ih       = (const float*)d_in[7];
    const float* W_hh       = (const float*)d_in[8];
    const float* b_ih       = (const float*)d_in[9];
    const float* b_hh       = (const float*)d_in[10];
    const float* w_trg_W    = (const float*)d_in[11];
    const float* w_trg_b    = (const float*)d_in[12];
    const float* w_att      = (const float*)d_in[13];
    const float* w_att_b    = (const float*)d_in[14];
    const float* ctx_W      = (const float*)d_in[15];
    const float* RW         = (const float*)d_in[16];
    float* out = (float*)d_out;

    cudaFuncSetAttribute(k_steps, cudaFuncAttributeMaxDynamicSharedMemorySize, STEPS_DYN);

    k_convB<<<(V * 128) / 256, 256>>>(RW);
    k_convWg<<<dim3(2, 4096), 256>>>(W_ih, W_hh);
    k_convWh<<<1024, 128>>>(w_trg_W);
    k_convWp<<<dim3(2, 1024), 192>>>(ctx_W);
    int init_total = 64 * 8192 + 32 * 1024 + 32 * 3072 + B * D;
    k_init0<<<(init_total + 255) / 256, 256>>>(h0, c0, word_emb, y_train);
    k_steps<<<GRIDN, 256, STEPS_DYN>>>(x_enc, x_enc_k, xm, y_train, word_emb,
                                       b_ih, b_hh, w_trg_b, w_att, w_att_b);
    k_logits_mma<<<dim3((B * TT) / 128, V / 128), 256>>>(out);
}

// round 16
// speedup vs baseline: 1.1233x; 1.0305x over previous
#include <cuda_runtime.h>
#include <cuda_bf16.h>
#include <math.h>
#include <stdint.h>

#define B  32
#define LX 64
#define TT 64
#define D  1024
#define V  32000
#define KPA 2048        // dedup A': [hi|lo]
#define KPB 2048        // dedup B': [hi|lo]
#define GRIDN 128
// dynamic ring for k_steps: mbar@0 (32B) | A stages 4x8192 @32 | B stages 4x16384 @32800
#define SC_ABASE 32
#define SC_BBASE 32800
#define STEPS_DYN (32 + 4 * 8192 + 4 * 16384)

// ------------------- device globals --------------------------------------------
__device__ float g_c[B * D];
__device__ float g_gatesp2[4 * 64 * 4096];
__device__ float g_hprojp2[16 * 64 * 1024];
__device__ float g_prep2[16 * 64 * 1024];
__device__ float g_wl[B * LX];
__device__ int g_bcnt[B];
// step-GEMM A operands, chunk-block layout [chunk][64][32] (4KB blocks)
__device__ __align__(16) __nv_bfloat16 g_A2g[256 * 64 * 32];
__device__ __align__(16) __nv_bfloat16 g_A2h[64 * 64 * 32];
__device__ __align__(16) __nv_bfloat16 g_A2p[192 * 64 * 32];
// logits operands (row-major, dedup [hi|lo])
__device__ __align__(16) __nv_bfloat16 g_Abf[(TT * B) * KPA];
__device__ __align__(16) __nv_bfloat16 g_Bbf[(size_t)V * KPB];
// weights, chunk-block layout [coltile][chunk][128][32] (8KB blocks)
__device__ __align__(16) __nv_bfloat16 g_Wg2[(size_t)32 * 256 * 128 * 32];
__device__ __align__(16) __nv_bfloat16 g_Wh2[8 * 64 * 128 * 32];
__device__ __align__(16) __nv_bfloat16 g_Wp2[8 * 192 * 128 * 32];
__device__ int g_flags[GRIDN];

// ------------------- helpers -----------------------------------------------------
__device__ __forceinline__ float fast_tanh(float x) {
    float e = __expf(2.f * x);
    return 1.f - __fdividef(2.f, e + 1.f);
}
__device__ __forceinline__ uint32_t smem_u32(const void* p) {
    uint32_t a;
    asm("{ .reg .u64 t; cvta.to.shared.u64 t, %1; cvt.u32.u64 %0, t; }" : "=r"(a) : "l"(p));
    return a;
}
__device__ __forceinline__ void cpasync16(uint32_t dst, const void* src) {
    asm volatile("cp.async.cg.shared.global [%0], [%1], 16;" :: "r"(dst), "l"(src));
}
__device__ __forceinline__ void ldm_x4(uint32_t* r, uint32_t addr) {
    asm volatile("ldmatrix.sync.aligned.m8n8.x4.shared.b16 {%0,%1,%2,%3}, [%4];"
        : "=r"(r[0]), "=r"(r[1]), "=r"(r[2]), "=r"(r[3]) : "r"(addr));
}
__device__ __forceinline__ void mma_bf16(float* c, const uint32_t* a, const uint32_t* b) {
    asm volatile("mma.sync.aligned.m16n8k16.row.col.f32.bf16.bf16.f32 "
        "{%0,%1,%2,%3}, {%4,%5,%6,%7}, {%8,%9}, {%0,%1,%2,%3};"
        : "+f"(c[0]), "+f"(c[1]), "+f"(c[2]), "+f"(c[3])
        : "r"(a[0]), "r"(a[1]), "r"(a[2]), "r"(a[3]), "r"(b[0]), "r"(b[1]));
}
__device__ __forceinline__ void split_bf(float v, __nv_bfloat16& hi, __nv_bfloat16& lo) {
    hi = __float2bfloat16_rn(v);
    lo = __float2bfloat16_rn(v - __bfloat162float(hi));
}
__device__ __forceinline__ uint32_t pk2(__nv_bfloat16 a, __nv_bfloat16 b) {
    __nv_bfloat162 t; t.x = a; t.y = b;
    return *(uint32_t*)&t;
}
__device__ __forceinline__ int swoff(int row, int kin) {
    return ((((kin >> 3) ^ ((row >> 1) & 3)) << 3) | (kin & 7));
}
__device__ __forceinline__ void a2st(__nv_bfloat16* base, int row, int k, __nv_bfloat16 v) {
    base[((k >> 5) * 64 + row) * 32 + swoff(row, k & 31)] = v;
}
__device__ __forceinline__ void a2st4(__nv_bfloat16* base, int row, int k,
                                      const __nv_bfloat16* h) {
    int off = ((k >> 5) * 64 + row) * 32
            + ((((k >> 3) & 3) ^ ((row >> 1) & 3)) << 3) + (k & 7);
    *(uint2*)(base + off) = make_uint2(pk2(h[0], h[1]), pk2(h[2], h[3]));
}
__device__ __forceinline__ void w2st8(__nv_bfloat16* base, int nch, int j, int k,
                                      const __nv_bfloat16* h) {
    size_t off = ((size_t)((j >> 7) * nch + (k >> 5)) * 128 + (j & 127)) * 32
               + ((((k >> 3) & 3) ^ (((j & 127) >> 1) & 3)) << 3);
    *(uint4*)(base + off) = make_uint4(pk2(h[0], h[1]), pk2(h[2], h[3]),
                                       pk2(h[4], h[5]), pk2(h[6], h[7]));
}
__device__ __forceinline__ void split8(const float* v, __nv_bfloat16* hi, __nv_bfloat16* lo) {
#pragma unroll
    for (int q = 0; q < 8; q++) split_bf(v[q], hi[q], lo[q]);
}
// ------------------- bulk copy + mbarrier ------------------------------------------
__device__ __forceinline__ void bulk_g2s(uint32_t dst, const void* src, uint32_t bytes,
                                         uint32_t mbar) {
    asm volatile(
        "cp.async.bulk.shared::cluster.global.mbarrier::complete_tx::bytes [%0], [%1], %2, [%3];"
        :: "r"(dst), "l"(src), "r"(bytes), "r"(mbar) : "memory");
}
__device__ __forceinline__ void mbar_expect(uint32_t mbar, uint32_t bytes) {
    asm volatile("mbarrier.arrive.expect_tx.shared.b64 _, [%0], %1;"
                 :: "r"(mbar), "r"(bytes) : "memory");
}
__device__ __forceinline__ void mbar_init1(uint32_t mbar) {
    asm volatile("mbarrier.init.shared.b64 [%0], 1;" :: "r"(mbar) : "memory");
}
__device__ __forceinline__ void mbar_wait(uint32_t mbar, uint32_t parity) {
    asm volatile(
        "{\n\t.reg .pred P;\n"
        "W%=:\n\t"
        "mbarrier.try_wait.parity.shared.b64 P, [%0], %1;\n\t"
        "@P bra D%=;\n\t"
        "bra W%=;\n"
        "D%=:\n\t}"
        :: "r"(mbar), "r"(parity) : "memory");
}
// issue one SUPER-chunk (two contiguous 32-k blocks) into ring stage idx&3
__device__ __forceinline__ void issue_super(uint32_t sb, unsigned idx,
        const __nv_bfloat16* __restrict__ Ablk,
        const __nv_bfloat16* __restrict__ Bblk, int chunk) {
    uint32_t st = idx & 3u, mb = sb + st * 8u;
    mbar_expect(mb, 24576u);
    bulk_g2s(sb + SC_ABASE + st * 8192u, Ablk + (size_t)chunk * 2048, 8192u, mb);
    bulk_g2s(sb + SC_BBASE + st * 16384u, Bblk + (size_t)chunk * 4096, 16384u, mb);
}
// ------------------- flag-array grid barrier -----------------------------------------
__device__ __forceinline__ void gridbar(unsigned gen) {
    asm volatile("fence.proxy.async;" ::: "memory");
    __threadfence();
    __syncthreads();
    if (threadIdx.x == 0) atomicExch(&g_flags[blockIdx.x], (int)gen);
    bool ok;
    do {
        ok = (threadIdx.x >= GRIDN) ||
             (__ldcg(&g_flags[threadIdx.x]) >= (int)gen);
    } while (!__syncthreads_and(ok));
}

// ------------------- init -----------------------------------------------------------
__global__ void k_init0(const float* __restrict__ h0, const float* __restrict__ c0,
                        const float* __restrict__ word_emb,
                        const int* __restrict__ y_train) {
    int i = blockIdx.x * 256 + threadIdx.x;
    if (i < GRIDN) g_flags[i] = 0;
    if (i < B) g_bcnt[i] = 0;
    if (i < 64 * 8192) {                 // gates A2 for t=0
        int r = i >> 13, k = i & 8191;
        int b = r & 31;
        bool isLo = r >= 32;
        int ks = (k < 4096) ? k : k - 4096;
        float v = 0.f;
        bool zero = (isLo && k >= 4096);
        if (!zero) {
            if (ks < 1024) {
                int y = y_train[b * TT + 0];
                v = word_emb[(size_t)y * D + ks];
            } else if (ks < 3072) {
                v = 0.f;
            } else {
                v = h0[b * D + (ks - 3072)];
            }
        }
        __nv_bfloat16 hi, lo; split_bf(v, hi, lo);
        a2st(g_A2g, r, k, zero ? __float2bfloat16_rn(0.f) : (isLo ? lo : hi));
        return;
    }
    int j = i - 64 * 8192;
    if (j < 32 * 1024) {
        int r = 32 + (j >> 10), k = 1024 + (j & 1023);
        a2st(g_A2h, r, k, __float2bfloat16_rn(0.f));
        return;
    }
    j -= 32 * 1024;
    if (j < 32 * 3072) {
        int r = 32 + j / 3072, k = 3072 + j % 3072;
        a2st(g_A2p, r, k, __float2bfloat16_rn(0.f));
        return;
    }
    j -= 32 * 3072;
    if (j < B * D) g_c[j] = c0[j];
}

// ------------------- weight conversions (vectorized 8k/thread) -----------------------
__global__ void k_convB(const float* __restrict__ RW) {
    int i = blockIdx.x * 256 + threadIdx.x;          // < V*128
    int r = i >> 7, d = (i & 127) * 8;
    float4 v0 = *(const float4*)(RW + (size_t)r * D + d);
    float4 v1 = *(const float4*)(RW + (size_t)r * D + d + 4);
    float v[8] = {v0.x, v0.y, v0.z, v0.w, v1.x, v1.y, v1.z, v1.w};
    __nv_bfloat16 hi[8], lo[8];
    split8(v, hi, lo);
    __nv_bfloat16* row = g_Bbf + (size_t)r * KPB;
    *(uint4*)(row + d) = make_uint4(pk2(hi[0], hi[1]), pk2(hi[2], hi[3]),
                                    pk2(hi[4], hi[5]), pk2(hi[6], hi[7]));
    *(uint4*)(row + 1024 + d) = make_uint4(pk2(lo[0], lo[1]), pk2(lo[2], lo[3]),
                                           pk2(lo[4], lo[5]), pk2(lo[6], lo[7]));
}
__global__ void k_convWg(const float* __restrict__ Wih, const float* __restrict__ Whh) {
    int kg = blockIdx.x * 256 + threadIdx.x;         // 0..511
    int j = blockIdx.y;
    int k = kg * 8;
    const float* src = (k < 3072) ? Wih + (size_t)j * 3072 + k
                                  : Whh + (size_t)j * 1024 + (k - 3072);
    float4 v0 = *(const float4*)src;
    float4 v1 = *(const float4*)(src + 4);
    float v[8] = {v0.x, v0.y, v0.z, v0.w, v1.x, v1.y, v1.z, v1.w};
    __nv_bfloat16 hi[8], lo[8];
    split8(v, hi, lo);
    w2st8(g_Wg2, 256, j, k, hi);
    w2st8(g_Wg2, 256, j, 4096 + k, lo);
}
__global__ void k_convWh(const float* __restrict__ Wt) {
    int kg = threadIdx.x;                            // 0..127
    int j = blockIdx.x;
    int k = kg * 8;
    float4 v0 = *(const float4*)(Wt + (size_t)j * 1024 + k);
    float4 v1 = *(const float4*)(Wt + (size_t)j * 1024 + k + 4);
    float v[8] = {v0.x, v0.y, v0.z, v0.w, v1.x, v1.y, v1.z, v1.w};
    __nv_bfloat16 hi[8], lo[8];
    split8(v, hi, lo);
    w2st8(g_Wh2, 64, j, k, hi);
    w2st8(g_Wh2, 64, j, 1024 + k, lo);
}
__global__ void k_convWp(const float* __restrict__ Cw) {
    int kg = blockIdx.x * 192 + threadIdx.x;         // 0..383
    int j = blockIdx.y;
    int k = kg * 8;
    float4 v0 = *(const float4*)(Cw + (size_t)j * 3072 + k);
    float4 v1 = *(const float4*)(Cw + (size_t)j * 3072 + k + 4);
    float v[8] = {v0.x, v0.y, v0.z, v0.w, v1.x, v1.y, v1.z, v1.w};
    __nv_bfloat16 hi[8], lo[8];
    split8(v, hi, lo);
    w2st8(g_Wp2, 192, j, k, hi);
    w2st8(g_Wp2, 192, j, 3072 + k, lo);
}

// ------------------- super-chunk 64xK @ Kx128 MMA phase (4-stage ring) ------------------
__device__ void mma_phase_bulk(uint32_t sb, unsigned& gsc,
        const __nv_bfloat16* __restrict__ Ablk,
        const __nv_bfloat16* __restrict__ Bblk,
        float* __restrict__ part, int ncols,
        int nsuper, int chunk0, int col0, int split) {
    int tid = threadIdx.x;
    int lane = tid & 31, wid = tid >> 5;
    int warpM = wid & 1, warpN = wid >> 1;

    int a_row = (lane & 7) + ((lane >> 3) & 1) * 8;
    int ca0 = lane >> 4;
    int b_row = (lane & 7) + (lane >> 4) * 8;
    int cb0 = (lane >> 3) & 1;
    int rA[2], sA_[2], rB[2], sB_[2];
#pragma unroll
    for (int mt = 0; mt < 2; mt++) {
        int r = warpM * 32 + mt * 16 + a_row;
        rA[mt] = r * 64; sA_[mt] = (r >> 1) & 3;
    }
#pragma unroll
    for (int p = 0; p < 2; p++) {
        int r = warpN * 32 + p * 16 + b_row;
        rB[p] = r * 64; sB_[p] = (r >> 1) & 3;
    }

    float acc[2][4][4] = {};

    if (tid == 0) {
        int npre = nsuper < 3 ? nsuper : 3;
        for (int j = 0; j < npre; j++)
            issue_super(sb, gsc + (unsigned)j, Ablk, Bblk, chunk0 + 2 * j);
    }
    for (int i = 0; i < nsuper; i++) {
        if (i + 3 < nsuper && tid == 0)
            issue_super(sb, gsc + (unsigned)(i + 3), Ablk, Bblk, chunk0 + 2 * (i + 3));
        unsigned idx = gsc + (unsigned)i;
        uint32_t st = idx & 3u;
        mbar_wait(sb + st * 8u, (idx >> 2) & 1u);
#pragma unroll
        for (int sub = 0; sub < 2; sub++) {
            uint32_t aOff = sb + SC_ABASE + st * 8192u + sub * 4096u;
            uint32_t bOff = sb + SC_BBASE + st * 16384u + sub * 8192u;
#pragma unroll
            for (int k16 = 0; k16 < 2; k16++) {
                int ca = ca0 + 2 * k16, cb = cb0 + 2 * k16;
                uint32_t a0[4], a1[4], bb[2][4];
                ldm_x4(a0, aOff + rA[0] + ((ca ^ sA_[0]) << 4));
                ldm_x4(a1, aOff + rA[1] + ((ca ^ sA_[1]) << 4));
                ldm_x4(bb[0], bOff + rB[0] + ((cb ^ sB_[0]) << 4));
                ldm_x4(bb[1], bOff + rB[1] + ((cb ^ sB_[1]) << 4));
#pragma unroll
                for (int nt = 0; nt < 4; nt++) {
                    mma_bf16(acc[0][nt], a0, &bb[nt >> 1][(nt & 1) * 2]);
                    mma_bf16(acc[1][nt], a1, &bb[nt >> 1][(nt & 1) * 2]);
                }
            }
        }
        __syncthreads();
    }
    gsc += (unsigned)nsuper;

    int grp = lane >> 2, tig = lane & 3;
#pragma unroll
    for (int mt = 0; mt < 2; mt++) {
        int m1 = warpM * 32 + mt * 16 + grp;
        int m2 = m1 + 8;
        float* p1 = part + (size_t)(split * 64 + m1) * ncols + col0 + warpN * 32;
        float* p2 = part + (size_t)(split * 64 + m2) * ncols + col0 + warpN * 32;
#pragma unroll
        for (int nt = 0; nt < 4; nt++) {
            int n = nt * 8 + tig * 2;
            *(float2*)(p1 + n) = make_float2(acc[mt][nt][0], acc[mt][nt][1]);
            *(float2*)(p2 + n) = make_float2(acc[mt][nt][2], acc[mt][nt][3]);
        }
    }
}

// ------------------- scalar phase work ------------------------------------------------
__device__ void emb_prefetch(int b, int tnext, const float* __restrict__ word_emb,
                             const int* __restrict__ y_train) {
    int d = threadIdx.x * 4;
    int y = y_train[b * TT + tnext];
    float4 v = *(const float4*)(word_emb + (size_t)y * D + d);
    float vv[4] = {v.x, v.y, v.z, v.w};
    __nv_bfloat16 hi[4], lo[4];
#pragma unroll
    for (int q = 0; q < 4; q++) split_bf(vv[q], hi[q], lo[q]);
    a2st4(g_A2g, b, d, hi);
    a2st4(g_A2g, b, 4096 + d, hi);
    a2st4(g_A2g, 32 + b, d, lo);
}

__device__ void cell_work(int bid, const float* __restrict__ b_ih,
                          const float* __restrict__ b_hh) {
    int tid = threadIdx.x;
    if (tid >= 64) return;
    int m = bid >> 2;
    int d = (bid & 3) * 256 + tid * 4;
    int id = m * 1024 + d;
    float gv[4][4];
#pragma unroll
    for (int g = 0; g < 4; g++) {
        float4 bi = *(const float4*)(b_ih + g * 1024 + d);
        float4 bh = *(const float4*)(b_hh + g * 1024 + d);
        gv[g][0] = bi.x + bh.x; gv[g][1] = bi.y + bh.y;
        gv[g][2] = bi.z + bh.z; gv[g][3] = bi.w + bh.w;
    }
#pragma unroll
    for (int s = 0; s < 4; s++) {
#pragma unroll
        for (int g = 0; g < 4; g++) {
            float4 p0 = __ldcg((const float4*)(g_gatesp2
                         + (size_t)(s * 64 + m) * 4096 + g * 1024 + d));
            float4 p1 = __ldcg((const float4*)(g_gatesp2
                         + (size_t)(s * 64 + 32 + m) * 4096 + g * 1024 + d));
            gv[g][0] += p0.x; gv[g][0] += p1.x;
            gv[g][1] += p0.y; gv[g][1] += p1.y;
            gv[g][2] += p0.z; gv[g][2] += p1.z;
            gv[g][3] += p0.w; gv[g][3] += p1.w;
        }
    }
    float4 cold = __ldcg((const float4*)&g_c[id]);
    float co[4] = {cold.x, cold.y, cold.z, cold.w};
    float4 cnew;
    float* cn = (float*)&cnew;
    __nv_bfloat16 hh[4], hl[4];
#pragma unroll
    for (int q = 0; q < 4; q++) {
        float si = 1.f / (1.f + expf(-gv[0][q]));
        float sf = 1.f / (1.f + expf(-gv[1][q]));
        float so = 1.f / (1.f + expf(-gv[3][q]));
        float c = sf * co[q] + si * tanhf(gv[2][q]);
        cn[q] = c;
        float h = so * tanhf(c);
        split_bf(h, hh[q], hl[q]);
    }
    a2st4(g_A2h, m, d, hh);        a2st4(g_A2h, m, 1024 + d, hh);
    a2st4(g_A2h, 32 + m, d, hl);
    a2st4(g_A2p, m, d, hh);        a2st4(g_A2p, m, 3072 + d, hh);
    a2st4(g_A2p, 32 + m, d, hl);
    a2st4(g_A2g, m, 3072 + d, hh); a2st4(g_A2g, m, 7168 + d, hh);
    a2st4(g_A2g, 32 + m, 3072 + d, hl);
    *(float4*)&g_c[id] = cnew;
}

__device__ void pretanh_work(int t, int bid) {
    int tid = threadIdx.x;
    if (tid >= 64) return;
    int m = bid >> 2;
    int d = (bid & 3) * 256 + tid * 4;
    float v[4] = {0.f, 0.f, 0.f, 0.f};
#pragma unroll
    for (int s = 0; s < 16; s++) {
        float4 p0 = __ldcg((const float4*)(g_prep2 + (size_t)(s * 64 + m) * 1024 + d));
        float4 p1 = __ldcg((const float4*)(g_prep2 + (size_t)(s * 64 + 32 + m) * 1024 + d));
        v[0] += p0.x; v[0] += p1.x;
        v[1] += p0.y; v[1] += p1.y;
        v[2] += p0.z; v[2] += p1.z;
        v[3] += p0.w; v[3] += p1.w;
    }
    int row = t * B + m;
    __nv_bfloat16* arow = g_Abf + (size_t)row * KPA;
    __nv_bfloat16 hi[4], lo[4];
#pragma unroll
    for (int q = 0; q < 4; q++) {
        float tv = tanhf(v[q]);
        split_bf(tv, hi[q], lo[q]);
    }
    *(uint2*)(arow + d)        = make_uint2(pk2(hi[0], hi[1]), pk2(hi[2], hi[3]));
    *(uint2*)(arow + 1024 + d) = make_uint2(pk2(lo[0], lo[1]), pk2(lo[2], lo[3]));
}

// merged attention phase: scores + 4-CTA local barrier + softmax + ctx
__device__ void attn_all(int bid, int t, float* s_hp, float* s_wl,
                         const float* __restrict__ x_enc,
                         const float* __restrict__ x_enc_k,
                         const unsigned char* __restrict__ xm,
                         const float* __restrict__ w_trg_b,
                         const float* __restrict__ w_att,
                         const float* __restrict__ w_att_b) {
    int b = bid >> 2;
    int quarter = bid & 3;
    int tid = threadIdx.x;
    int lane = tid & 31, wd = tid >> 5;
    // finalize hproj partials
    {
        int d4 = tid * 4;
        float4 bi = *(const float4*)(w_trg_b + d4);
        float sum[4] = {bi.x, bi.y, bi.z, bi.w};
#pragma unroll
        for (int s = 0; s < 16; s++) {
            float4 p0 = __ldcg((const float4*)(g_hprojp2
                        + (size_t)(s * 64 + b) * 1024 + d4));
            float4 p1 = __ldcg((const float4*)(g_hprojp2
                        + (size_t)(s * 64 + 32 + b) * 1024 + d4));
            sum[0] += p0.x; sum[0] += p1.x;
            sum[1] += p0.y; sum[1] += p1.y;
            sum[2] += p0.z; sum[2] += p1.z;
            sum[3] += p0.w; sum[3] += p1.w;
        }
        *(float4*)&s_hp[d4] = make_float4(sum[0], sum[1], sum[2], sum[3]);
    }
    __syncthreads();
    // scores: 16 l per CTA
    for (int l = quarter * 16 + wd; l < quarter * 16 + 16; l += 8) {
        const float* xk = x_enc_k + ((size_t)(b * LX + l)) * D;
        float s = 0.f;
#pragma unroll 8
        for (int i = 0; i < 32; i++) {
            int d = lane + i * 32;
            s += fast_tanh(xk[d] + s_hp[d]) * w_att[d];
        }
#pragma unroll
        for (int off = 16; off; off >>= 1) s += __shfl_xor_sync(0xffffffffu, s, off);
        if (lane == 0) {
            float tot = s + w_att_b[0];
            if (xm[b * LX + l]) tot = -1e9f;
            g_wl[b * LX + l] = tot;
        }
    }
    // 4-CTA local barrier for batch row b
    __threadfence();
    __syncthreads();
    if (tid == 0) {
        atomicAdd(&g_bcnt[b], 1);
        int target = 4 * (t + 1);
        while (__ldcg(&g_bcnt[b]) < target) { }
        __threadfence();
    }
    __syncthreads();
    // softmax (serial per CTA, identical across the 4 CTAs of b)
    if (tid == 0) {
        float tmp[LX];
        float mx = -1e30f;
        for (int l = 0; l < LX; l++) {
            float v = __ldcg(&g_wl[b * LX + l]);
            tmp[l] = v;
            mx = fmaxf(mx, v);
        }
        float z = 0.f;
        for (int l = 0; l < LX; l++) { float e = expf(tmp[l] - mx); tmp[l] = e; z += e; }
        float inv = 1.f / z;
        for (int l = 0; l < LX; l++) s_wl[l] = tmp[l] * inv;
    }
    __syncthreads();
    // ctx over this CTA's 512-dim quarter
    {
        int half = tid >> 7;
        int dt = (tid & 127) * 4;
        int d2 = quarter * 512 + dt;
        const float* xe = x_enc + (size_t)b * LX * 2048 + d2;
        float f[4] = {0.f, 0.f, 0.f, 0.f};
        int l0 = half * 32;
#pragma unroll 8
        for (int l = l0; l < l0 + 32; l++) {
            float w = s_wl[l];
            float4 x0 = *(const float4*)(xe + (size_t)l * 2048);
            f[0] += w * x0.x; f[1] += w * x0.y; f[2] += w * x0.z; f[3] += w * x0.w;
        }
        if (half == 0) {
            *(float4*)&s_hp[dt] = make_float4(f[0], f[1], f[2], f[3]);
        }
        __syncthreads();
        if (half == 1) {
            float4 o = *(const float4*)&s_hp[dt];
            f[0] += o.x; f[1] += o.y; f[2] += o.z; f[3] += o.w;
            int dd = 1024 + d2;
            __nv_bfloat16 hi[4], lo[4];
#pragma unroll
            for (int q = 0; q < 4; q++) split_bf(f[q], hi[q], lo[q]);
            a2st4(g_A2p, b, dd, hi);        a2st4(g_A2p, b, 3072 + dd, hi);
            a2st4(g_A2p, 32 + b, dd, lo);
            a2st4(g_A2g, b, dd, hi);        a2st4(g_A2g, b, 4096 + dd, hi);
            a2st4(g_A2g, 32 + b, dd, lo);
        }
    }
}

// ------------------- persistent step kernel --------------------------------------------
__global__ void __launch_bounds__(256, 1) k_steps(
    const float* __restrict__ x_enc, const float* __restrict__ x_enc_k,
    const unsigned char* __restrict__ xm, const int* __restrict__ y_train,
    const float* __restrict__ word_emb,
    const float* __restrict__ b_ih, const float* __restrict__ b_hh,
    const float* __restrict__ w_trg_b, const float* __restrict__ w_att,
    const float* __restrict__ w_att_b) {
    extern __shared__ __align__(128) char s_ring[];
    __shared__ float s_hp[1024];
    __shared__ float s_wl[LX];
    uint32_t sb = smem_u32(s_ring);
    int bid = blockIdx.x;
    int tid = threadIdx.x;
    unsigned gen = 0, gsc = 0;

    if (tid == 0) {
        mbar_init1(sb); mbar_init1(sb + 8); mbar_init1(sb + 16); mbar_init1(sb + 24);
    }
    __syncthreads();

    const __nv_bfloat16* Wg = g_Wg2 + (size_t)(bid & 31) * 256 * 4096;
    int g_chunk0 = (bid >> 5) * 64;

    for (int t = 0; t < TT; t++) {
        // phase 1: gates MMA (32 super-chunks)
        mma_phase_bulk(sb, gsc, g_A2g, Wg, g_gatesp2, 4096, 32,
                       g_chunk0, (bid & 31) * 128, bid >> 5);
        gridbar(++gen);
        // phase 2: LSTM cell + pretanh(t-1) + emb(t+1)
        cell_work(bid, b_ih, b_hh);
        if (t > 0) pretanh_work(t - 1, bid);
        if (bid < 32 && t + 1 < TT) emb_prefetch(bid, t + 1, word_emb, y_train);
        gridbar(++gen);
        // phase 3: hproj MMA (2 super-chunks)
        mma_phase_bulk(sb, gsc, g_A2h,
                       g_Wh2 + (size_t)(bid & 7) * 64 * 4096,
                       g_hprojp2, 1024, 2, (bid >> 3) * 4, (bid & 7) * 128,
                       bid >> 3);
        gridbar(++gen);
        // phase 4: scores + local 4-CTA barrier + softmax + ctx
        attn_all(bid, t, s_hp, s_wl, x_enc, x_enc_k, xm, w_trg_b, w_att, w_att_b);
        gridbar(++gen);
        // phase 5: pre MMA (6 super-chunks, no trailing barrier)
        mma_phase_bulk(sb, gsc, g_A2p,
                       g_Wp2 + (size_t)(bid & 7) * 192 * 4096,
                       g_prep2, 1024, 6, (bid >> 3) * 12, (bid & 7) * 128,
                       bid >> 3);
    }
    gridbar(++gen);
    pretanh_work(TT - 1, bid);
}

// ------------------- logits GEMM (R14/R15, known passing) --------------------------------
__global__ void __launch_bounds__(256, 2) k_logits_mma(float* __restrict__ out) {
    __shared__ __align__(16) __nv_bfloat16 sA[2][128][40];
    __shared__ __align__(16) __nv_bfloat16 sB[2][128][40];
    int tid = threadIdx.x;
    int lane = tid & 31, wid = tid >> 5;
    int warpM = wid & 1, warpN = wid >> 1;
    int row0 = blockIdx.x * 128;
    int col0 = blockIdx.y * 128;

    int a_row = (lane & 7) + ((lane >> 3) & 1) * 8;
    int a_k   = (lane >> 4) * 8;
    int b_row = (lane & 7) + (lane >> 4) * 8;
    int b_k   = ((lane >> 3) & 1) * 8;
    uint32_t aBase = smem_u32(&sA[0][0][0]) + (warpM * 64 + a_row) * 80 + a_k * 2;
    uint32_t bBase = smem_u32(&sB[0][0][0]) + (warpN * 32 + b_row) * 80 + b_k * 2;

    int ldr = tid >> 2;
    int ldi = tid & 3;

    float acc[4][4][4];
#pragma unroll
    for (int i = 0; i < 4; i++)
#pragma unroll
        for (int j = 0; j < 4; j++)
#pragma unroll
            for (int q = 0; q < 4; q++) acc[i][j][q] = 0.f;

#pragma unroll
    for (int q = 0; q < 2; q++) {
        int r = ldr + q * 64;
        cpasync16(smem_u32(&sA[0][r][ldi * 8]), g_Abf + (size_t)(row0 + r) * KPA + ldi * 8);
        cpasync16(smem_u32(&sB[0][r][ldi * 8]), g_Bbf + (size_t)(col0 + r) * KPB + ldi * 8);
    }
    asm volatile("cp.async.commit_group;" ::: "memory");

    const int NCH = 96;
    for (int i = 0; i < NCH; i++) {
        int st = i & 1;
        if (i + 1 < NCH) {
            int ns = st ^ 1;
            int i1 = i + 1;
            int kbA = (i1 < 64 ? i1 : i1 - 64) * 32;
            int kbB = (i1 < 32 ? i1 : i1 - 32) * 32;
#pragma unroll
            for (int q = 0; q < 2; q++) {
                int r = ldr + q * 64;
                cpasync16(smem_u32(&sA[ns][r][ldi * 8]),
                          g_Abf + (size_t)(row0 + r) * KPA + kbA + ldi * 8);
                cpasync16(smem_u32(&sB[ns][r][ldi * 8]),
                          g_Bbf + (size_t)(col0 + r) * KPB + kbB + ldi * 8);
            }
            asm volatile("cp.async.commit_group;" ::: "memory");
            asm volatile("cp.async.wait_group 1;" ::: "memory");
        } else {
            asm volatile("cp.async.wait_group 0;" ::: "memory");
        }
        __syncthreads();

        uint32_t stoff = st * (uint32_t)(128 * 80);
#pragma unroll
        for (int k16 = 0; k16 < 2; k16++) {
            uint32_t koff = stoff + k16 * 32;
            uint32_t a[4][4], b[2][4];
#pragma unroll
            for (int mt = 0; mt < 4; mt++) ldm_x4(a[mt], aBase + koff + mt * 1280);
#pragma unroll
            for (int p = 0; p < 2; p++)    ldm_x4(b[p], bBase + koff + p * 1280);
#pragma unroll
            for (int mt = 0; mt < 4; mt++)
#pragma unroll
                for (int nt = 0; nt < 4; nt++)
                    mma_bf16(acc[mt][nt], a[mt], &b[nt >> 1][(nt & 1) * 2]);
        }
        __syncthreads();
    }

    int grp = lane >> 2, tig = lane & 3;
#pragma unroll
    for (int mt = 0; mt < 4; mt++) {
        int m1 = row0 + warpM * 64 + mt * 16 + grp;
        int m2 = m1 + 8;
        float* o1 = out + ((size_t)(m1 & 31) * TT + (m1 >> 5)) * V;
        float* o2 = out + ((size_t)(m2 & 31) * TT + (m2 >> 5)) * V;
#pragma unroll
        for (int nt = 0; nt < 4; nt++) {
            int n = col0 + warpN * 32 + nt * 8 + tig * 2;
            *(float2*)(o1 + n) = make_float2(acc[mt][nt][0], acc[mt][nt][1]);
            *(float2*)(o2 + n) = make_float2(acc[mt][nt][2], acc[mt][nt][3]);
        }
    }
}

// ------------------- launch ---------------------------------------------------------------
extern "C" void kernel_launch(void* const* d_in, const int* in_sizes, int n_in,
                              void* d_out, int out_size) {
    const float* x_enc      = (const float*)d_in[0];
    const float* x_enc_k    = (const float*)d_in[1];
    const float* h0         = (const float*)d_in[2];
    const float* c0         = (const float*)d_in[3];
    const unsigned char* xm = (const unsigned char*)d_in[4];
    const int*   y_train    = (const int*)d_in[5];
    const float* word_emb   = (const float*)d_in[6];
    const float* W_ih       = (const float*)d_in[7];
    const float* W_hh       = (const float*)d_in[8];
    const float* b_ih       = (const float*)d_in[9];
    const float* b_hh       = (const float*)d_in[10];
    const float* w_trg_W    = (const float*)d_in[11];
    const float* w_trg_b    = (const float*)d_in[12];
    const float* w_att      = (const float*)d_in[13];
    const float* w_att_b    = (const float*)d_in[14];
    const float* ctx_W      = (const float*)d_in[15];
    const float* RW         = (const float*)d_in[16];
    float* out = (float*)d_out;

    cudaFuncSetAttribute(k_steps, cudaFuncAttributeMaxDynamicSharedMemorySize, STEPS_DYN);

    k_convB<<<(V * 128) / 256, 256>>>(RW);
    k_convWg<<<dim3(2, 4096), 256>>>(W_ih, W_hh);
    k_convWh<<<1024, 128>>>(w_trg_W);
    k_convWp<<<dim3(2, 1024), 192>>>(ctx_W);
    int init_total = 64 * 8192 + 32 * 1024 + 32 * 3072 + B * D;
    k_init0<<<(init_total + 255) / 256, 256>>>(h0, c0, word_emb, y_train);
    k_steps<<<GRIDN, 256, STEPS_DYN>>>(x_enc, x_enc_k, xm, y_train, word_emb,
                                       b_ih, b_hh, w_trg_b, w_att, w_att_b);
    k_logits_mma<<<dim3((B * TT) / 128, V / 128), 256>>>(out);
}

// round 17
// speedup vs baseline: 1.1463x; 1.0205x over previous
#include <cuda_runtime.h>
#include <cuda_bf16.h>
#include <math.h>
#include <stdint.h>

#define B  32
#define LX 64
#define TT 64
#define D  1024
#define V  32000
#define KPA 2048        // dedup A': [hi|lo]
#define KPB 2048        // dedup B': [hi|lo]
#define GRIDN 128
// dynamic smem for k_steps:
// mbar@0 (32B) | A stages 4x8192 @32 | B stages 4x16384 @32800 | Wh persist 32KB @98336
#define SC_ABASE 32
#define SC_BBASE 32800
#define SC_WHBASE 98336
#define STEPS_DYN (32 + 4 * 8192 + 4 * 16384 + 32768)

// ------------------- device globals --------------------------------------------
__device__ float g_c[B * D];
__device__ float g_gatesp2[4 * 64 * 4096];
__device__ float g_hprojp2[16 * 64 * 1024];
__device__ float g_prep2[16 * 64 * 1024];
__device__ float g_wl[B * LX];
__device__ int g_bcnt[B];
// step-GEMM A operands, chunk-block layout [chunk][64][32] (4KB blocks)
__device__ __align__(16) __nv_bfloat16 g_A2g[256 * 64 * 32];
__device__ __align__(16) __nv_bfloat16 g_A2h[64 * 64 * 32];
__device__ __align__(16) __nv_bfloat16 g_A2p[192 * 64 * 32];
// logits operands (row-major, dedup [hi|lo])
__device__ __align__(16) __nv_bfloat16 g_Abf[(TT * B) * KPA];
__device__ __align__(16) __nv_bfloat16 g_Bbf[(size_t)V * KPB];
// weights, chunk-block layout [coltile][chunk][128][32] (8KB blocks)
__device__ __align__(16) __nv_bfloat16 g_Wg2[(size_t)32 * 256 * 128 * 32];
__device__ __align__(16) __nv_bfloat16 g_Wh2[8 * 64 * 128 * 32];
__device__ __align__(16) __nv_bfloat16 g_Wp2[8 * 192 * 128 * 32];
__device__ int g_flags[GRIDN];

// ------------------- helpers -----------------------------------------------------
__device__ __forceinline__ float fast_tanh(float x) {
    float e = __expf(2.f * x);
    return 1.f - __fdividef(2.f, e + 1.f);
}
__device__ __forceinline__ uint32_t smem_u32(const void* p) {
    uint32_t a;
    asm("{ .reg .u64 t; cvta.to.shared.u64 t, %1; cvt.u32.u64 %0, t; }" : "=r"(a) : "l"(p));
    return a;
}
__device__ __forceinline__ void cpasync16(uint32_t dst, const void* src) {
    asm volatile("cp.async.cg.shared.global [%0], [%1], 16;" :: "r"(dst), "l"(src));
}
__device__ __forceinline__ void ldm_x4(uint32_t* r, uint32_t addr) {
    asm volatile("ldmatrix.sync.aligned.m8n8.x4.shared.b16 {%0,%1,%2,%3}, [%4];"
        : "=r"(r[0]), "=r"(r[1]), "=r"(r[2]), "=r"(r[3]) : "r"(addr));
}
__device__ __forceinline__ void mma_bf16(float* c, const uint32_t* a, const uint32_t* b) {
    asm volatile("mma.sync.aligned.m16n8k16.row.col.f32.bf16.bf16.f32 "
        "{%0,%1,%2,%3}, {%4,%5,%6,%7}, {%8,%9}, {%0,%1,%2,%3};"
        : "+f"(c[0]), "+f"(c[1]), "+f"(c[2]), "+f"(c[3])
        : "r"(a[0]), "r"(a[1]), "r"(a[2]), "r"(a[3]), "r"(b[0]), "r"(b[1]));
}
__device__ __forceinline__ void split_bf(float v, __nv_bfloat16& hi, __nv_bfloat16& lo) {
    hi = __float2bfloat16_rn(v);
    lo = __float2bfloat16_rn(v - __bfloat162float(hi));
}
__device__ __forceinline__ uint32_t pk2(__nv_bfloat16 a, __nv_bfloat16 b) {
    __nv_bfloat162 t; t.x = a; t.y = b;
    return *(uint32_t*)&t;
}
__device__ __forceinline__ int swoff(int row, int kin) {
    return ((((kin >> 3) ^ ((row >> 1) & 3)) << 3) | (kin & 7));
}
__device__ __forceinline__ void a2st(__nv_bfloat16* base, int row, int k, __nv_bfloat16 v) {
    base[((k >> 5) * 64 + row) * 32 + swoff(row, k & 31)] = v;
}
__device__ __forceinline__ void a2st4(__nv_bfloat16* base, int row, int k,
                                      const __nv_bfloat16* h) {
    int off = ((k >> 5) * 64 + row) * 32
            + ((((k >> 3) & 3) ^ ((row >> 1) & 3)) << 3) + (k & 7);
    *(uint2*)(base + off) = make_uint2(pk2(h[0], h[1]), pk2(h[2], h[3]));
}
__device__ __forceinline__ void w2st8(__nv_bfloat16* base, int nch, int j, int k,
                                      const __nv_bfloat16* h) {
    size_t off = ((size_t)((j >> 7) * nch + (k >> 5)) * 128 + (j & 127)) * 32
               + ((((k >> 3) & 3) ^ (((j & 127) >> 1) & 3)) << 3);
    *(uint4*)(base + off) = make_uint4(pk2(h[0], h[1]), pk2(h[2], h[3]),
                                       pk2(h[4], h[5]), pk2(h[6], h[7]));
}
__device__ __forceinline__ void split8(const float* v, __nv_bfloat16* hi, __nv_bfloat16* lo) {
#pragma unroll
    for (int q = 0; q < 8; q++) split_bf(v[q], hi[q], lo[q]);
}
// ------------------- bulk copy + mbarrier ------------------------------------------
__device__ __forceinline__ void bulk_g2s(uint32_t dst, const void* src, uint32_t bytes,
                                         uint32_t mbar) {
    asm volatile(
        "cp.async.bulk.shared::cluster.global.mbarrier::complete_tx::bytes [%0], [%1], %2, [%3];"
        :: "r"(dst), "l"(src), "r"(bytes), "r"(mbar) : "memory");
}
__device__ __forceinline__ void mbar_expect(uint32_t mbar, uint32_t bytes) {
    asm volatile("mbarrier.arrive.expect_tx.shared.b64 _, [%0], %1;"
                 :: "r"(mbar), "r"(bytes) : "memory");
}
__device__ __forceinline__ void mbar_init1(uint32_t mbar) {
    asm volatile("mbarrier.init.shared.b64 [%0], 1;" :: "r"(mbar) : "memory");
}
__device__ __forceinline__ void mbar_wait(uint32_t mbar, uint32_t parity) {
    asm volatile(
        "{\n\t.reg .pred P;\n"
        "W%=:\n\t"
        "mbarrier.try_wait.parity.shared.b64 P, [%0], %1;\n\t"
        "@P bra D%=;\n\t"
        "bra W%=;\n"
        "D%=:\n\t}"
        :: "r"(mbar), "r"(parity) : "memory");
}
// issue one SUPER-chunk into ring stage idx&3; aonly => B is smem-persistent
__device__ __forceinline__ void issue_super(uint32_t sb, unsigned idx,
        const __nv_bfloat16* __restrict__ Ablk,
        const __nv_bfloat16* __restrict__ Bblk, int chunk, bool aonly) {
    uint32_t st = idx & 3u, mb = sb + st * 8u;
    if (aonly) {
        mbar_expect(mb, 8192u);
        bulk_g2s(sb + SC_ABASE + st * 8192u, Ablk + (size_t)chunk * 2048, 8192u, mb);
    } else {
        mbar_expect(mb, 24576u);
        bulk_g2s(sb + SC_ABASE + st * 8192u, Ablk + (size_t)chunk * 2048, 8192u, mb);
        bulk_g2s(sb + SC_BBASE + st * 16384u, Bblk + (size_t)chunk * 4096, 16384u, mb);
    }
}
// ------------------- flag-array grid barrier -----------------------------------------
__device__ __forceinline__ void gridbar(unsigned gen) {
    asm volatile("fence.proxy.async;" ::: "memory");
    __threadfence();
    __syncthreads();
    if (threadIdx.x == 0) atomicExch(&g_flags[blockIdx.x], (int)gen);
    bool ok;
    do {
        ok = (threadIdx.x >= GRIDN) ||
             (__ldcg(&g_flags[threadIdx.x]) >= (int)gen);
        if (!ok) __nanosleep(32);
    } while (!__syncthreads_and(ok));
}

// ------------------- init -----------------------------------------------------------
__global__ void k_init0(const float* __restrict__ h0, const float* __restrict__ c0,
                        const float* __restrict__ word_emb,
                        const int* __restrict__ y_train) {
    int i = blockIdx.x * 256 + threadIdx.x;
    if (i < GRIDN) g_flags[i] = 0;
    if (i < B) g_bcnt[i] = 0;
    if (i < 64 * 8192) {                 // gates A2 for t=0
        int r = i >> 13, k = i & 8191;
        int b = r & 31;
        bool isLo = r >= 32;
        int ks = (k < 4096) ? k : k - 4096;
        float v = 0.f;
        bool zero = (isLo && k >= 4096);
        if (!zero) {
            if (ks < 1024) {
                int y = y_train[b * TT + 0];
                v = word_emb[(size_t)y * D + ks];
            } else if (ks < 3072) {
                v = 0.f;
            } else {
                v = h0[b * D + (ks - 3072)];
            }
        }
        __nv_bfloat16 hi, lo; split_bf(v, hi, lo);
        a2st(g_A2g, r, k, zero ? __float2bfloat16_rn(0.f) : (isLo ? lo : hi));
        return;
    }
    int j = i - 64 * 8192;
    if (j < 32 * 1024) {
        int r = 32 + (j >> 10), k = 1024 + (j & 1023);
        a2st(g_A2h, r, k, __float2bfloat16_rn(0.f));
        return;
    }
    j -= 32 * 1024;
    if (j < 32 * 3072) {
        int r = 32 + j / 3072, k = 3072 + j % 3072;
        a2st(g_A2p, r, k, __float2bfloat16_rn(0.f));
        return;
    }
    j -= 32 * 3072;
    if (j < B * D) g_c[j] = c0[j];
}

// ------------------- weight conversions (vectorized 8k/thread) -----------------------
__global__ void k_convB(const float* __restrict__ RW) {
    int i = blockIdx.x * 256 + threadIdx.x;
    int r = i >> 7, d = (i & 127) * 8;
    float4 v0 = *(const float4*)(RW + (size_t)r * D + d);
    float4 v1 = *(const float4*)(RW + (size_t)r * D + d + 4);
    float v[8] = {v0.x, v0.y, v0.z, v0.w, v1.x, v1.y, v1.z, v1.w};
    __nv_bfloat16 hi[8], lo[8];
    split8(v, hi, lo);
    __nv_bfloat16* row = g_Bbf + (size_t)r * KPB;
    *(uint4*)(row + d) = make_uint4(pk2(hi[0], hi[1]), pk2(hi[2], hi[3]),
                                    pk2(hi[4], hi[5]), pk2(hi[6], hi[7]));
    *(uint4*)(row + 1024 + d) = make_uint4(pk2(lo[0], lo[1]), pk2(lo[2], lo[3]),
                                           pk2(lo[4], lo[5]), pk2(lo[6], lo[7]));
}
__global__ void k_convWg(const float* __restrict__ Wih, const float* __restrict__ Whh) {
    int kg = blockIdx.x * 256 + threadIdx.x;
    int j = blockIdx.y;
    int k = kg * 8;
    const float* src = (k < 3072) ? Wih + (size_t)j * 3072 + k
                                  : Whh + (size_t)j * 1024 + (k - 3072);
    float4 v0 = *(const float4*)src;
    float4 v1 = *(const float4*)(src + 4);
    float v[8] = {v0.x, v0.y, v0.z, v0.w, v1.x, v1.y, v1.z, v1.w};
    __nv_bfloat16 hi[8], lo[8];
    split8(v, hi, lo);
    w2st8(g_Wg2, 256, j, k, hi);
    w2st8(g_Wg2, 256, j, 4096 + k, lo);
}
__global__ void k_convWh(const float* __restrict__ Wt) {
    int kg = threadIdx.x;
    int j = blockIdx.x;
    int k = kg * 8;
    float4 v0 = *(const float4*)(Wt + (size_t)j * 1024 + k);
    float4 v1 = *(const float4*)(Wt + (size_t)j * 1024 + k + 4);
    float v[8] = {v0.x, v0.y, v0.z, v0.w, v1.x, v1.y, v1.z, v1.w};
    __nv_bfloat16 hi[8], lo[8];
    split8(v, hi, lo);
    w2st8(g_Wh2, 64, j, k, hi);
    w2st8(g_Wh2, 64, j, 1024 + k, lo);
}
__global__ void k_convWp(const float* __restrict__ Cw) {
    int kg = blockIdx.x * 192 + threadIdx.x;
    int j = blockIdx.y;
    int k = kg * 8;
    float4 v0 = *(const float4*)(Cw + (size_t)j * 3072 + k);
    float4 v1 = *(const float4*)(Cw + (size_t)j * 3072 + k + 4);
    float v[8] = {v0.x, v0.y, v0.z, v0.w, v1.x, v1.y, v1.z, v1.w};
    __nv_bfloat16 hi[8], lo[8];
    split8(v, hi, lo);
    w2st8(g_Wp2, 192, j, k, hi);
    w2st8(g_Wp2, 192, j, 3072 + k, lo);
}

// ------------------- super-chunk 64xK @ Kx128 MMA phase (4-stage ring) ------------------
// persistB != 0: B operand is resident in smem at persistB; issue A only.
__device__ void mma_phase_bulk(uint32_t sb, unsigned& gsc,
        const __nv_bfloat16* __restrict__ Ablk,
        const __nv_bfloat16* __restrict__ Bblk,
        float* __restrict__ part, int ncols,
        int nsuper, int chunk0, int col0, int split, uint32_t persistB) {
    int tid = threadIdx.x;
    int lane = tid & 31, wid = tid >> 5;
    int warpM = wid & 1, warpN = wid >> 1;
    bool aonly = persistB != 0u;

    int a_row = (lane & 7) + ((lane >> 3) & 1) * 8;
    int ca0 = lane >> 4;
    int b_row = (lane & 7) + (lane >> 4) * 8;
    int cb0 = (lane >> 3) & 1;
    int rA[2], sA_[2], rB[2], sB_[2];
#pragma unroll
    for (int mt = 0; mt < 2; mt++) {
        int r = warpM * 32 + mt * 16 + a_row;
        rA[mt] = r * 64; sA_[mt] = (r >> 1) & 3;
    }
#pragma unroll
    for (int p = 0; p < 2; p++) {
        int r = warpN * 32 + p * 16 + b_row;
        rB[p] = r * 64; sB_[p] = (r >> 1) & 3;
    }

    float acc[2][4][4] = {};

    if (tid == 0) {
        int npre = nsuper < 3 ? nsuper : 3;
        for (int j = 0; j < npre; j++)
            issue_super(sb, gsc + (unsigned)j, Ablk, Bblk, chunk0 + 2 * j, aonly);
    }
    for (int i = 0; i < nsuper; i++) {
        if (i + 3 < nsuper && tid == 0)
            issue_super(sb, gsc + (unsigned)(i + 3), Ablk, Bblk, chunk0 + 2 * (i + 3), aonly);
        unsigned idx = gsc + (unsigned)i;
        uint32_t st = idx & 3u;
        mbar_wait(sb + st * 8u, (idx >> 2) & 1u);
#pragma unroll
        for (int sub = 0; sub < 2; sub++) {
            uint32_t aOff = sb + SC_ABASE + st * 8192u + sub * 4096u;
            uint32_t bOff = aonly ? (persistB + (uint32_t)(2 * i + sub) * 8192u)
                                  : (sb + SC_BBASE + st * 16384u + sub * 8192u);
#pragma unroll
            for (int k16 = 0; k16 < 2; k16++) {
                int ca = ca0 + 2 * k16, cb = cb0 + 2 * k16;
                uint32_t a0[4], a1[4], bb[2][4];
                ldm_x4(a0, aOff + rA[0] + ((ca ^ sA_[0]) << 4));
                ldm_x4(a1, aOff + rA[1] + ((ca ^ sA_[1]) << 4));
                ldm_x4(bb[0], bOff + rB[0] + ((cb ^ sB_[0]) << 4));
                ldm_x4(bb[1], bOff + rB[1] + ((cb ^ sB_[1]) << 4));
#pragma unroll
                for (int nt = 0; nt < 4; nt++) {
                    mma_bf16(acc[0][nt], a0, &bb[nt >> 1][(nt & 1) * 2]);
                    mma_bf16(acc[1][nt], a1, &bb[nt >> 1][(nt & 1) * 2]);
                }
            }
        }
        __syncthreads();
    }
    gsc += (unsigned)nsuper;

    int grp = lane >> 2, tig = lane & 3;
#pragma unroll
    for (int mt = 0; mt < 2; mt++) {
        int m1 = warpM * 32 + mt * 16 + grp;
        int m2 = m1 + 8;
        float* p1 = part + (size_t)(split * 64 + m1) * ncols + col0 + warpN * 32;
        float* p2 = part + (size_t)(split * 64 + m2) * ncols + col0 + warpN * 32;
#pragma unroll
        for (int nt = 0; nt < 4; nt++) {
            int n = nt * 8 + tig * 2;
            *(float2*)(p1 + n) = make_float2(acc[mt][nt][0], acc[mt][nt][1]);
            *(float2*)(p2 + n) = make_float2(acc[mt][nt][2], acc[mt][nt][3]);
        }
    }
}

// ------------------- scalar phase work ------------------------------------------------
__device__ void emb_prefetch(int b, int tnext, const float* __restrict__ word_emb,
                             const int* __restrict__ y_train) {
    int d = threadIdx.x * 4;
    int y = y_train[b * TT + tnext];
    float4 v = *(const float4*)(word_emb + (size_t)y * D + d);
    float vv[4] = {v.x, v.y, v.z, v.w};
    __nv_bfloat16 hi[4], lo[4];
#pragma unroll
    for (int q = 0; q < 4; q++) split_bf(vv[q], hi[q], lo[q]);
    a2st4(g_A2g, b, d, hi);
    a2st4(g_A2g, b, 4096 + d, hi);
    a2st4(g_A2g, 32 + b, d, lo);
}

__device__ void cell_work(int bid, const float* __restrict__ b_ih,
                          const float* __restrict__ b_hh) {
    int tid = threadIdx.x;
    if (tid >= 64) return;
    int m = bid >> 2;
    int d = (bid & 3) * 256 + tid * 4;
    int id = m * 1024 + d;
    float gv[4][4];
#pragma unroll
    for (int g = 0; g < 4; g++) {
        float4 bi = *(const float4*)(b_ih + g * 1024 + d);
        float4 bh = *(const float4*)(b_hh + g * 1024 + d);
        gv[g][0] = bi.x + bh.x; gv[g][1] = bi.y + bh.y;
        gv[g][2] = bi.z + bh.z; gv[g][3] = bi.w + bh.w;
    }
#pragma unroll
    for (int s = 0; s < 4; s++) {
#pragma unroll
        for (int g = 0; g < 4; g++) {
            float4 p0 = __ldcg((const float4*)(g_gatesp2
                         + (size_t)(s * 64 + m) * 4096 + g * 1024 + d));
            float4 p1 = __ldcg((const float4*)(g_gatesp2
                         + (size_t)(s * 64 + 32 + m) * 4096 + g * 1024 + d));
            gv[g][0] += p0.x; gv[g][0] += p1.x;
            gv[g][1] += p0.y; gv[g][1] += p1.y;
            gv[g][2] += p0.z; gv[g][2] += p1.z;
            gv[g][3] += p0.w; gv[g][3] += p1.w;
        }
    }
    float4 cold = __ldcg((const float4*)&g_c[id]);
    float co[4] = {cold.x, cold.y, cold.z, cold.w};
    float4 cnew;
    float* cn = (float*)&cnew;
    __nv_bfloat16 hh[4], hl[4];
#pragma unroll
    for (int q = 0; q < 4; q++) {
        float si = 1.f / (1.f + expf(-gv[0][q]));
        float sf = 1.f / (1.f + expf(-gv[1][q]));
        float so = 1.f / (1.f + expf(-gv[3][q]));
        float c = sf * co[q] + si * tanhf(gv[2][q]);
        cn[q] = c;
        float h = so * tanhf(c);
        split_bf(h, hh[q], hl[q]);
    }
    a2st4(g_A2h, m, d, hh);        a2st4(g_A2h, m, 1024 + d, hh);
    a2st4(g_A2h, 32 + m, d, hl);
    a2st4(g_A2p, m, d, hh);        a2st4(g_A2p, m, 3072 + d, hh);
    a2st4(g_A2p, 32 + m, d, hl);
    a2st4(g_A2g, m, 3072 + d, hh); a2st4(g_A2g, m, 7168 + d, hh);
    a2st4(g_A2g, 32 + m, 3072 + d, hl);
    *(float4*)&g_c[id] = cnew;
}

__device__ void pretanh_work(int t, int bid) {
    int tid = threadIdx.x;
    if (tid >= 64) return;
    int m = bid >> 2;
    int d = (bid & 3) * 256 + tid * 4;
    float v[4] = {0.f, 0.f, 0.f, 0.f};
#pragma unroll
    for (int s = 0; s < 16; s++) {
        float4 p0 = __ldcg((const float4*)(g_prep2 + (size_t)(s * 64 + m) * 1024 + d));
        float4 p1 = __ldcg((const float4*)(g_prep2 + (size_t)(s * 64 + 32 + m) * 1024 + d));
        v[0] += p0.x; v[0] += p1.x;
        v[1] += p0.y; v[1] += p1.y;
        v[2] += p0.z; v[2] += p1.z;
        v[3] += p0.w; v[3] += p1.w;
    }
    int row = t * B + m;
    __nv_bfloat16* arow = g_Abf + (size_t)row * KPA;
    __nv_bfloat16 hi[4], lo[4];
#pragma unroll
    for (int q = 0; q < 4; q++) {
        float tv = tanhf(v[q]);
        split_bf(tv, hi[q], lo[q]);
    }
    *(uint2*)(arow + d)        = make_uint2(pk2(hi[0], hi[1]), pk2(hi[2], hi[3]));
    *(uint2*)(arow + 1024 + d) = make_uint2(pk2(lo[0], lo[1]), pk2(lo[2], lo[3]));
}

// merged attention phase: scores + 4-CTA local barrier + parallel softmax + ctx
__device__ void attn_all(int bid, int t, float* s_hp, float* s_wl,
                         const float* __restrict__ x_enc,
                         const float* __restrict__ x_enc_k,
                         const unsigned char* __restrict__ xm,
                         const float* __restrict__ w_trg_b,
                         const float* __restrict__ w_att,
                         const float* __restrict__ w_att_b) {
    int b = bid >> 2;
    int quarter = bid & 3;
    int tid = threadIdx.x;
    int lane = tid & 31, wd = tid >> 5;
    // finalize hproj partials
    {
        int d4 = tid * 4;
        float4 bi = *(const float4*)(w_trg_b + d4);
        float sum[4] = {bi.x, bi.y, bi.z, bi.w};
#pragma unroll
        for (int s = 0; s < 16; s++) {
            float4 p0 = __ldcg((const float4*)(g_hprojp2
                        + (size_t)(s * 64 + b) * 1024 + d4));
            float4 p1 = __ldcg((const float4*)(g_hprojp2
                        + (size_t)(s * 64 + 32 + b) * 1024 + d4));
            sum[0] += p0.x; sum[0] += p1.x;
            sum[1] += p0.y; sum[1] += p1.y;
            sum[2] += p0.z; sum[2] += p1.z;
            sum[3] += p0.w; sum[3] += p1.w;
        }
        *(float4*)&s_hp[d4] = make_float4(sum[0], sum[1], sum[2], sum[3]);
    }
    __syncthreads();
    // scores: 16 l per CTA
    for (int l = quarter * 16 + wd; l < quarter * 16 + 16; l += 8) {
        const float* xk = x_enc_k + ((size_t)(b * LX + l)) * D;
        float s = 0.f;
#pragma unroll 8
        for (int i = 0; i < 32; i++) {
            int d = lane + i * 32;
            s += fast_tanh(xk[d] + s_hp[d]) * w_att[d];
        }
#pragma unroll
        for (int off = 16; off; off >>= 1) s += __shfl_xor_sync(0xffffffffu, s, off);
        if (lane == 0) {
            float tot = s + w_att_b[0];
            if (xm[b * LX + l]) tot = -1e9f;
            g_wl[b * LX + l] = tot;
        }
    }
    // 4-CTA local barrier for batch row b
    __threadfence();
    __syncthreads();
    if (tid == 0) {
        atomicAdd(&g_bcnt[b], 1);
        int target = 4 * (t + 1);
        while (__ldcg(&g_bcnt[b]) < target) { }
        __threadfence();
    }
    __syncthreads();
    // parallel softmax (warp 0: 2 l per lane, shuffle reductions)
    if (wd == 0) {
        float v0 = __ldcg(&g_wl[b * LX + lane]);
        float v1 = __ldcg(&g_wl[b * LX + 32 + lane]);
        float mx = fmaxf(v0, v1);
#pragma unroll
        for (int off = 16; off; off >>= 1)
            mx = fmaxf(mx, __shfl_xor_sync(0xffffffffu, mx, off));
        float e0 = expf(v0 - mx), e1 = expf(v1 - mx);
        float z = e0 + e1;
#pragma unroll
        for (int off = 16; off; off >>= 1) z += __shfl_xor_sync(0xffffffffu, z, off);
        float inv = 1.f / z;
        s_wl[lane] = e0 * inv;
        s_wl[32 + lane] = e1 * inv;
    }
    __syncthreads();
    // ctx over this CTA's 512-dim quarter
    {
        int half = tid >> 7;
        int dt = (tid & 127) * 4;
        int d2 = quarter * 512 + dt;
        const float* xe = x_enc + (size_t)b * LX * 2048 + d2;
        float f[4] = {0.f, 0.f, 0.f, 0.f};
        int l0 = half * 32;
#pragma unroll 8
        for (int l = l0; l < l0 + 32; l++) {
            float w = s_wl[l];
            float4 x0 = *(const float4*)(xe + (size_t)l * 2048);
            f[0] += w * x0.x; f[1] += w * x0.y; f[2] += w * x0.z; f[3] += w * x0.w;
        }
        if (half == 0) {
            *(float4*)&s_hp[dt] = make_float4(f[0], f[1], f[2], f[3]);
        }
        __syncthreads();
        if (half == 1) {
            float4 o = *(const float4*)&s_hp[dt];
            f[0] += o.x; f[1] += o.y; f[2] += o.z; f[3] += o.w;
            int dd = 1024 + d2;
            __nv_bfloat16 hi[4], lo[4];
#pragma unroll
            for (int q = 0; q < 4; q++) split_bf(f[q], hi[q], lo[q]);
            a2st4(g_A2p, b, dd, hi);        a2st4(g_A2p, b, 3072 + dd, hi);
            a2st4(g_A2p, 32 + b, dd, lo);
            a2st4(g_A2g, b, dd, hi);        a2st4(g_A2g, b, 4096 + dd, hi);
            a2st4(g_A2g, 32 + b, dd, lo);
        }
    }
}

// ------------------- persistent step kernel --------------------------------------------
__global__ void __launch_bounds__(256, 1) k_steps(
    const float* __restrict__ x_enc, const float* __restrict__ x_enc_k,
    const unsigned char* __restrict__ xm, const int* __restrict__ y_train,
    const float* __restrict__ word_emb,
    const float* __restrict__ b_ih, const float* __restrict__ b_hh,
    const float* __restrict__ w_trg_b, const float* __restrict__ w_att,
    const float* __restrict__ w_att_b) {
    extern __shared__ __align__(128) char s_ring[];
    __shared__ float s_hp[1024];
    __shared__ float s_wl[LX];
    uint32_t sb = smem_u32(s_ring);
    int bid = blockIdx.x;
    int tid = threadIdx.x;
    unsigned gen = 0, gsc = 0;

    if (tid == 0) {
        mbar_init1(sb); mbar_init1(sb + 8); mbar_init1(sb + 16); mbar_init1(sb + 24);
    }
    // one-time load of this CTA's hproj B slice (4 chunks = 32KB) into persist region
    {
        const uint4* whsrc = (const uint4*)(g_Wh2 + (size_t)(bid & 7) * 64 * 4096
                                            + (size_t)((bid >> 3) * 4) * 4096);
        uint4* whdst = (uint4*)(s_ring + SC_WHBASE);
        for (int i = tid; i < 2048; i += 256) whdst[i] = __ldcg(whsrc + i);
    }
    __syncthreads();

    const __nv_bfloat16* Wg = g_Wg2 + (size_t)(bid & 31) * 256 * 4096;
    int g_chunk0 = (bid >> 5) * 64;
    uint32_t whbase = sb + SC_WHBASE;

    for (int t = 0; t < TT; t++) {
        // phase 1: gates MMA (32 super-chunks)
        mma_phase_bulk(sb, gsc, g_A2g, Wg, g_gatesp2, 4096, 32,
                       g_chunk0, (bid & 31) * 128, bid >> 5, 0u);
        gridbar(++gen);
        // phase 2: LSTM cell + pretanh(t-1) + emb(t+1)
        cell_work(bid, b_ih, b_hh);
        if (t > 0) pretanh_work(t - 1, bid);
        if (bid < 32 && t + 1 < TT) emb_prefetch(bid, t + 1, word_emb, y_train);
        gridbar(++gen);
        // phase 3: hproj MMA (2 super-chunks, B persistent in smem, A-only bulks)
        mma_phase_bulk(sb, gsc, g_A2h, (const __nv_bfloat16*)0,
                       g_hprojp2, 1024, 2, (bid >> 3) * 4, (bid & 7) * 128,
                       bid >> 3, whbase);
        gridbar(++gen);
        // phase 4: scores + local 4-CTA barrier + softmax + ctx
        attn_all(bid, t, s_hp, s_wl, x_enc, x_enc_k, xm, w_trg_b, w_att, w_att_b);
        gridbar(++gen);
        // phase 5: pre MMA (6 super-chunks, no trailing barrier)
        mma_phase_bulk(sb, gsc, g_A2p,
                       g_Wp2 + (size_t)(bid & 7) * 192 * 4096,
                       g_prep2, 1024, 6, (bid >> 3) * 12, (bid & 7) * 128,
                       bid >> 3, 0u);
    }
    gridbar(++gen);
    pretanh_work(TT - 1, bid);
}

// ------------------- logits GEMM (R14/R15/R16, known passing) ----------------------------
__global__ void __launch_bounds__(256, 2) k_logits_mma(float* __restrict__ out) {
    __shared__ __align__(16) __nv_bfloat16 sA[2][128][40];
    __shared__ __align__(16) __nv_bfloat16 sB[2][128][40];
    int tid = threadIdx.x;
    int lane = tid & 31, wid = tid >> 5;
    int warpM = wid & 1, warpN = wid >> 1;
    int row0 = blockIdx.x * 128;
    int col0 = blockIdx.y * 128;

    int a_row = (lane & 7) + ((lane >> 3) & 1) * 8;
    int a_k   = (lane >> 4) * 8;
    int b_row = (lane & 7) + (lane >> 4) * 8;
    int b_k   = ((lane >> 3) & 1) * 8;
    uint32_t aBase = smem_u32(&sA[0][0][0]) + (warpM * 64 + a_row) * 80 + a_k * 2;
    uint32_t bBase = smem_u32(&sB[0][0][0]) + (warpN * 32 + b_row) * 80 + b_k * 2;

    int ldr = tid >> 2;
    int ldi = tid & 3;

    float acc[4][4][4];
#pragma unroll
    for (int i = 0; i < 4; i++)
#pragma unroll
        for (int j = 0; j < 4; j++)
#pragma unroll
            for (int q = 0; q < 4; q++) acc[i][j][q] = 0.f;

#pragma unroll
    for (int q = 0; q < 2; q++) {
        int r = ldr + q * 64;
        cpasync16(smem_u32(&sA[0][r][ldi * 8]), g_Abf + (size_t)(row0 + r) * KPA + ldi * 8);
        cpasync16(smem_u32(&sB[0][r][ldi * 8]), g_Bbf + (size_t)(col0 + r) * KPB + ldi * 8);
    }
    asm volatile("cp.async.commit_group;" ::: "memory");

    const int NCH = 96;
    for (int i = 0; i < NCH; i++) {
        int st = i & 1;
        if (i + 1 < NCH) {
            int ns = st ^ 1;
            int i1 = i + 1;
            int kbA = (i1 < 64 ? i1 : i1 - 64) * 32;
            int kbB = (i1 < 32 ? i1 : i1 - 32) * 32;
#pragma unroll
            for (int q = 0; q < 2; q++) {
                int r = ldr + q * 64;
                cpasync16(smem_u32(&sA[ns][r][ldi * 8]),
                          g_Abf + (size_t)(row0 + r) * KPA + kbA + ldi * 8);
                cpasync16(smem_u32(&sB[ns][r][ldi * 8]),
                          g_Bbf + (size_t)(col0 + r) * KPB + kbB + ldi * 8);
            }
            asm volatile("cp.async.commit_group;" ::: "memory");
            asm volatile("cp.async.wait_group 1;" ::: "memory");
        } else {
            asm volatile("cp.async.wait_group 0;" ::: "memory");
        }
        __syncthreads();

        uint32_t stoff = st * (uint32_t)(128 * 80);
#pragma unroll
        for (int k16 = 0; k16 < 2; k16++) {
            uint32_t koff = stoff + k16 * 32;
            uint32_t a[4][4], b[2][4];
#pragma unroll
            for (int mt = 0; mt < 4; mt++) ldm_x4(a[mt], aBase + koff + mt * 1280);
#pragma unroll
            for (int p = 0; p < 2; p++)    ldm_x4(b[p], bBase + koff + p * 1280);
#pragma unroll
            for (int mt = 0; mt < 4; mt++)
#pragma unroll
                for (int nt = 0; nt < 4; nt++)
                    mma_bf16(acc[mt][nt], a[mt], &b[nt >> 1][(nt & 1) * 2]);
        }
        __syncthreads();
    }

    int grp = lane >> 2, tig = lane & 3;
#pragma unroll
    for (int mt = 0; mt < 4; mt++) {
        int m1 = row0 + warpM * 64 + mt * 16 + grp;
        int m2 = m1 + 8;
        float* o1 = out + ((size_t)(m1 & 31) * TT + (m1 >> 5)) * V;
        float* o2 = out + ((size_t)(m2 & 31) * TT + (m2 >> 5)) * V;
#pragma unroll
        for (int nt = 0; nt < 4; nt++) {
            int n = col0 + warpN * 32 + nt * 8 + tig * 2;
            *(float2*)(o1 + n) = make_float2(acc[mt][nt][0], acc[mt][nt][1]);
            *(float2*)(o2 + n) = make_float2(acc[mt][nt][2], acc[mt][nt][3]);
        }
    }
}

// ------------------- launch ---------------------------------------------------------------
extern "C" void kernel_launch(void* const* d_in, const int* in_sizes, int n_in,
                              void* d_out, int out_size) {
    const float* x_enc      = (const float*)d_in[0];
    const float* x_enc_k    = (const float*)d_in[1];
    const float* h0         = (const float*)d_in[2];
    const float* c0         = (const float*)d_in[3];
    const unsigned char* xm = (const unsigned char*)d_in[4];
    const int*   y_train    = (const int*)d_in[5];
    const float* word_emb   = (const float*)d_in[6];
    const float* W_ih       = (const float*)d_in[7];
    const float* W_hh       = (const float*)d_in[8];
    const float* b_ih       = (const float*)d_in[9];
    const float* b_hh       = (const float*)d_in[10];
    const float* w_trg_W    = (const float*)d_in[11];
    const float* w_trg_b    = (const float*)d_in[12];
    const float* w_att      = (const float*)d_in[13];
    const float* w_att_b    = (const float*)d_in[14];
    const float* ctx_W      = (const float*)d_in[15];
    const float* RW         = (const float*)d_in[16];
    float* out = (float*)d_out;

    cudaFuncSetAttribute(k_steps, cudaFuncAttributeMaxDynamicSharedMemorySize, STEPS_DYN);

    k_convB<<<(V * 128) / 256, 256>>>(RW);
    k_convWg<<<dim3(2, 4096), 256>>>(W_ih, W_hh);
    k_convWh<<<1024, 128>>>(w_trg_W);
    k_convWp<<<dim3(2, 1024), 192>>>(ctx_W);
    int init_total = 64 * 8192 + 32 * 1024 + 32 * 3072 + B * D;
    k_init0<<<(init_total + 255) / 256, 256>>>(h0, c0, word_emb, y_train);
    k_steps<<<GRIDN, 256, STEPS_DYN>>>(x_enc, x_enc_k, xm, y_train, word_emb,
                                       b_ih, b_hh, w_trg_b, w_att, w_att_b);
    k_logits_mma<<<dim3((B * TT) / 128, V / 128), 256>>>(out);
}